// round 1
// baseline (speedup 1.0000x reference)
#include <cuda_runtime.h>
#include <math.h>

// Problem dims
#define Bb 8
#define Ss 4096
#define Hh 512
#define Kdim 512
#define Ndim 512
#define Mtot (Bb*Ss)      // 32768

#define CHUNKS 32
#define TLEN (Ss/CHUNKS)  // 128

// Scratch (allocation-free rule: device globals)
__device__ float g_a [(size_t)Mtot*Hh];   // 1 - z
__device__ float g_b [(size_t)Mtot*Hh];   // z * g(p)
__device__ float g_h1[(size_t)Mtot*Hh];   // layer-0 hidden sequence
__device__ float g_cA[Bb*CHUNKS*Hh];
__device__ float g_cB[Bb*CHUNKS*Hh];
__device__ float g_hs[Bb*CHUNKS*Hh];

// ---------------------------------------------------------------------------
// Dual GEMM: computes k = X @ Wz^T + bz and p = X @ Wh^T + bh for a
// 128(M) x 64(N) tile, sharing the A tile between both weight matrices.
// Fused epilogue writes a = sigmoid(-k), b = sigmoid(k) * g(p).
// ---------------------------------------------------------------------------
#define BM 128
#define BN 64
#define BK 16
#define TM 8
#define TN 4

__global__ __launch_bounds__(256, 2)
void gemm_dual(const float* __restrict__ Xin,
               const float* __restrict__ Wz, const float* __restrict__ bz,
               const float* __restrict__ Wh, const float* __restrict__ bh)
{
    const float* X = Xin ? Xin : g_h1;

    __shared__ float As [BK][BM+4];
    __shared__ float Bzs[BK][BN+4];
    __shared__ float Bhs[BK][BN+4];

    const int tid      = threadIdx.x;          // 256 threads
    const int blockRow = blockIdx.y * BM;
    const int blockCol = blockIdx.x * BN;

    const int lr = tid >> 2;                   // 0..63
    const int lc = (tid & 3) << 2;             // 0,4,8,12

    const int tc = (tid & 15) * TN;            // 0..60
    const int tr = (tid >> 4) * TM;            // 0..120

    float accZ[TM][TN];
    float accH[TM][TN];
#pragma unroll
    for (int i = 0; i < TM; i++)
#pragma unroll
        for (int j = 0; j < TN; j++) { accZ[i][j] = 0.f; accH[i][j] = 0.f; }

    const float* Ap  = X  + (size_t)blockRow * Kdim;
    const float* Wzp = Wz + (size_t)blockCol * Kdim;
    const float* Whp = Wh + (size_t)blockCol * Kdim;

    for (int k0 = 0; k0 < Kdim; k0 += BK) {
        float4 va0 = *(const float4*)(Ap  + (size_t)(lr     ) * Kdim + k0 + lc);
        float4 va1 = *(const float4*)(Ap  + (size_t)(lr + 64) * Kdim + k0 + lc);
        float4 vz  = *(const float4*)(Wzp + (size_t)(lr     ) * Kdim + k0 + lc);
        float4 vh  = *(const float4*)(Whp + (size_t)(lr     ) * Kdim + k0 + lc);

        As [lc+0][lr   ] = va0.x; As [lc+1][lr   ] = va0.y;
        As [lc+2][lr   ] = va0.z; As [lc+3][lr   ] = va0.w;
        As [lc+0][lr+64] = va1.x; As [lc+1][lr+64] = va1.y;
        As [lc+2][lr+64] = va1.z; As [lc+3][lr+64] = va1.w;
        Bzs[lc+0][lr]    = vz.x;  Bzs[lc+1][lr]    = vz.y;
        Bzs[lc+2][lr]    = vz.z;  Bzs[lc+3][lr]    = vz.w;
        Bhs[lc+0][lr]    = vh.x;  Bhs[lc+1][lr]    = vh.y;
        Bhs[lc+2][lr]    = vh.z;  Bhs[lc+3][lr]    = vh.w;

        __syncthreads();

#pragma unroll
        for (int kk = 0; kk < BK; kk++) {
            float4 a0  = *(const float4*)&As [kk][tr];
            float4 a1  = *(const float4*)&As [kk][tr+4];
            float4 bz4 = *(const float4*)&Bzs[kk][tc];
            float4 bh4 = *(const float4*)&Bhs[kk][tc];

            float ra[TM] = {a0.x,a0.y,a0.z,a0.w,a1.x,a1.y,a1.z,a1.w};
            float rz[TN] = {bz4.x,bz4.y,bz4.z,bz4.w};
            float rh[TN] = {bh4.x,bh4.y,bh4.z,bh4.w};
#pragma unroll
            for (int i = 0; i < TM; i++) {
#pragma unroll
                for (int j = 0; j < TN; j++) {
                    accZ[i][j] = fmaf(ra[i], rz[j], accZ[i][j]);
                    accH[i][j] = fmaf(ra[i], rh[j], accH[i][j]);
                }
            }
        }
        __syncthreads();
    }

    // Fused activation epilogue
    float bzr[TN], bhr[TN];
#pragma unroll
    for (int j = 0; j < TN; j++) {
        bzr[j] = bz[blockCol + tc + j];
        bhr[j] = bh[blockCol + tc + j];
    }

#pragma unroll
    for (int i = 0; i < TM; i++) {
        const int m = blockRow + tr + i;
        const size_t off = (size_t)m * Ndim + blockCol + tc;
        float4 av, bv;
        float oa[TN], ob[TN];
#pragma unroll
        for (int j = 0; j < TN; j++) {
            float kv = accZ[i][j] + bzr[j];
            float pv = accH[i][j] + bhr[j];
            float e  = expf(-kv);
            float z  = 1.0f / (1.0f + e);     // sigmoid(k)
            float az = e * z;                 // 1 - z  (exact form)
            float ht = (pv >= 0.f) ? (pv + 0.5f) : (1.0f / (1.0f + expf(-pv)));
            oa[j] = az;
            ob[j] = z * ht;
        }
        av.x = oa[0]; av.y = oa[1]; av.z = oa[2]; av.w = oa[3];
        bv.x = ob[0]; bv.y = ob[1]; bv.z = ob[2]; bv.w = ob[3];
        *(float4*)&g_a[off] = av;
        *(float4*)&g_b[off] = bv;
    }
}

// ---------------------------------------------------------------------------
// Chunked affine scan: h_t = a_t * h_{t-1} + b_t  along S, per (b,h) channel.
// ---------------------------------------------------------------------------

// Pass 1: per-chunk composed affine (A, B)
__global__ void scan_pass1()
{
    const int h = threadIdx.x;       // 512
    const int c = blockIdx.x;        // 32 chunks
    const int b = blockIdx.y;        // 8 batches
    size_t base = ((size_t)b * Ss + (size_t)c * TLEN) * Hh + h;

    float A = 1.f, Bv = 0.f;
#pragma unroll 4
    for (int t = 0; t < TLEN; t++) {
        float at = g_a[base + (size_t)t * Hh];
        float bt = g_b[base + (size_t)t * Hh];
        Bv = fmaf(at, Bv, bt);
        A *= at;
    }
    int idx = (b * CHUNKS + c) * Hh + h;
    g_cA[idx] = A;
    g_cB[idx] = Bv;
}

// Pass 2: stitch chunk boundaries (sequential over 32 chunks)
__global__ void scan_pass2()
{
    const int h = threadIdx.x;
    const int b = blockIdx.x;
    float hv = 0.5f;                 // h0 = g(0) = 0.5
    for (int c = 0; c < CHUNKS; c++) {
        int idx = (b * CHUNKS + c) * Hh + h;
        g_hs[idx] = hv;
        hv = fmaf(g_cA[idx], hv, g_cB[idx]);
    }
}

// Pass 3: replay each chunk from its boundary state, emit hidden sequence
__global__ void scan_pass3(float* outOrNull, float* __restrict__ finalDst)
{
    const int h = threadIdx.x;
    const int c = blockIdx.x;
    const int b = blockIdx.y;
    float* out = outOrNull ? outOrNull : g_h1;

    size_t base = ((size_t)b * Ss + (size_t)c * TLEN) * Hh + h;
    float hv = g_hs[(b * CHUNKS + c) * Hh + h];
#pragma unroll 4
    for (int t = 0; t < TLEN; t++) {
        size_t o = base + (size_t)t * Hh;
        hv = fmaf(g_a[o], hv, g_b[o]);
        out[o] = hv;
    }
    if (c == CHUNKS - 1)
        finalDst[b * Hh + h] = hv;
}

// ---------------------------------------------------------------------------
extern "C" void kernel_launch(void* const* d_in, const int* in_sizes, int n_in,
                              void* d_out, int out_size)
{
    const float* x   = (const float*)d_in[0];
    const float* wz0 = (const float*)d_in[1];
    const float* bz0 = (const float*)d_in[2];
    const float* wh0 = (const float*)d_in[3];
    const float* bh0 = (const float*)d_in[4];
    const float* wz1 = (const float*)d_in[5];
    const float* bz1 = (const float*)d_in[6];
    const float* wh1 = (const float*)d_in[7];
    const float* bh1 = (const float*)d_in[8];

    float* out    = (float*)d_out;
    float* finals = out + (size_t)Mtot * Hh;   // (L,B,1,H) tail

    dim3 gg(Ndim / BN, Mtot / BM);   // 8 x 256
    dim3 sg(CHUNKS, Bb);             // 32 x 8

    // Layer 0: input x -> g_h1, finals[0]
    gemm_dual<<<gg, 256>>>(x, wz0, bz0, wh0, bh0);
    scan_pass1<<<sg, Hh>>>();
    scan_pass2<<<Bb, Hh>>>();
    scan_pass3<<<sg, Hh>>>(nullptr, finals);

    // Layer 1: input g_h1 -> out, finals[1]
    gemm_dual<<<gg, 256>>>(nullptr, wz1, bz1, wh1, bh1);
    scan_pass1<<<sg, Hh>>>();
    scan_pass2<<<Bb, Hh>>>();
    scan_pass3<<<sg, Hh>>>(out, finals + Bb * Hh);
}

// round 3
// speedup vs baseline: 1.5916x; 1.5916x over previous
#include <cuda_runtime.h>
#include <cuda_bf16.h>
#include <math.h>
#include <stdint.h>

#define Bb 8
#define Ss 4096
#define Hn 512
#define Kd 512
#define Mtot (Bb*Ss)          // 32768
#define CHUNKS 64
#define TLEN (Ss/CHUNKS)      // 64

// ------------------------- scratch (device globals) -------------------------
__device__ __align__(256) __nv_bfloat16 g_xh[(size_t)Mtot*Kd];
__device__ __align__(256) __nv_bfloat16 g_xl[(size_t)Mtot*Kd];
__device__ __align__(256) float2        g_ab[(size_t)Mtot*Hn];
__device__ __align__(256) float2        g_cAB[Bb*CHUNKS*Hn];
__device__ __align__(256) float         g_hs [Bb*CHUNKS*Hn];
// 0..3: wz0 hi, wz0 lo, wh0 hi, wh0 lo ; 4..7: layer 1
__device__ __align__(256) __nv_bfloat16 g_w[8][(size_t)Kd*Hn];

// ------------------------------ helpers ------------------------------------
__device__ __forceinline__ uint32_t s2u(const void* p) {
    uint32_t a;
    asm("{ .reg .u64 t; cvta.to.shared.u64 t, %1; cvt.u32.u64 %0, t; }"
        : "=r"(a) : "l"(p));
    return a;
}

__device__ __forceinline__ void cpa16(uint32_t dst, const void* src) {
    asm volatile("cp.async.cg.shared.global [%0], [%1], 16;" :: "r"(dst), "l"(src));
}

__device__ __forceinline__ void mma_bf16(float* d, const uint32_t* a,
                                         uint32_t b0, uint32_t b1) {
    asm volatile(
        "mma.sync.aligned.m16n8k16.row.col.f32.bf16.bf16.f32 "
        "{%0,%1,%2,%3}, {%4,%5,%6,%7}, {%8,%9}, {%0,%1,%2,%3};"
        : "+f"(d[0]), "+f"(d[1]), "+f"(d[2]), "+f"(d[3])
        : "r"(a[0]), "r"(a[1]), "r"(a[2]), "r"(a[3]), "r"(b0), "r"(b1));
}

// ------------------------------- conversions -------------------------------
__global__ void conv_x_kern(const float* __restrict__ src) {
    int i = blockIdx.x * blockDim.x + threadIdx.x;   // over Mtot*Kd/4
    float4 v = ((const float4*)src)[i];
    __nv_bfloat16 hx = __float2bfloat16(v.x), hy = __float2bfloat16(v.y);
    __nv_bfloat16 hz = __float2bfloat16(v.z), hw = __float2bfloat16(v.w);
    __nv_bfloat16 lx = __float2bfloat16(v.x - __bfloat162float(hx));
    __nv_bfloat16 ly = __float2bfloat16(v.y - __bfloat162float(hy));
    __nv_bfloat16 lz = __float2bfloat16(v.z - __bfloat162float(hz));
    __nv_bfloat16 lw = __float2bfloat16(v.w - __bfloat162float(hw));
    __nv_bfloat162 p0; p0.x = hx; p0.y = hy;
    __nv_bfloat162 p1; p1.x = hz; p1.y = hw;
    __nv_bfloat162 q0; q0.x = lx; q0.y = ly;
    __nv_bfloat162 q1; q1.x = lz; q1.y = lw;
    ((__nv_bfloat162*)g_xh)[2*i  ] = p0;
    ((__nv_bfloat162*)g_xh)[2*i+1] = p1;
    ((__nv_bfloat162*)g_xl)[2*i  ] = q0;
    ((__nv_bfloat162*)g_xl)[2*i+1] = q1;
}

__global__ void conv_w_kern(const float* __restrict__ src, int widx) {
    int i = blockIdx.x * blockDim.x + threadIdx.x;   // over Kd*Hn/4
    float4 v = ((const float4*)src)[i];
    __nv_bfloat16 hx = __float2bfloat16(v.x), hy = __float2bfloat16(v.y);
    __nv_bfloat16 hz = __float2bfloat16(v.z), hw = __float2bfloat16(v.w);
    __nv_bfloat16 lx = __float2bfloat16(v.x - __bfloat162float(hx));
    __nv_bfloat16 ly = __float2bfloat16(v.y - __bfloat162float(hy));
    __nv_bfloat16 lz = __float2bfloat16(v.z - __bfloat162float(hz));
    __nv_bfloat16 lw = __float2bfloat16(v.w - __bfloat162float(hw));
    __nv_bfloat162 p0; p0.x = hx; p0.y = hy;
    __nv_bfloat162 p1; p1.x = hz; p1.y = hw;
    __nv_bfloat162 q0; q0.x = lx; q0.y = ly;
    __nv_bfloat162 q1; q1.x = lz; q1.y = lw;
    ((__nv_bfloat162*)g_w[widx    ])[2*i  ] = p0;
    ((__nv_bfloat162*)g_w[widx    ])[2*i+1] = p1;
    ((__nv_bfloat162*)g_w[widx + 1])[2*i  ] = q0;
    ((__nv_bfloat162*)g_w[widx + 1])[2*i+1] = q1;
}

// --------------------------- mma.sync dual GEMM -----------------------------
// CTA tile: 128 M x 64 N, two f32 accumulators (Z and H) per output.
// K pipelined in chunks of 32 with 3-stage cp.async.
// smem stage layout (bytes): AH 0..10240, AL 10240.., then 4 W tiles of 5120:
// WZH 20480, WZL 25600, WHH 30720, WHL 35840. Row stride 40 bf16 (80B).
#define KC 32
#define STAGES 3
#define STAGE_BYTES 40960
#define SMEM_BYTES (STAGES*STAGE_BYTES)
#define NCHUNK (Kd/KC)   // 16

__device__ __forceinline__ void load_stage(uint32_t sb,
    const __nv_bfloat16* Ah, const __nv_bfloat16* Al,
    const __nv_bfloat16* const* Wp,
    int rowBase, int colBase, int kOff, int tid)
{
#pragma unroll
    for (int i = 0; i < 4; i++) {
        int idx  = tid + i * 256;        // 0..1023
        int tile = idx >> 9;             // 0=hi, 1=lo
        int r    = (idx >> 2) & 127;
        int seg  = idx & 3;
        const __nv_bfloat16* src = (tile ? Al : Ah)
            + (size_t)(rowBase + r) * Kd + kOff + seg * 8;
        uint32_t dst = sb + tile * 10240 + r * 80 + seg * 16;
        cpa16(dst, src);
    }
#pragma unroll
    for (int i = 0; i < 4; i++) {
        int idx  = tid + i * 256;        // 0..1023
        int tile = idx >> 8;             // 0..3
        int r    = (idx >> 2) & 63;
        int seg  = idx & 3;
        const __nv_bfloat16* src = Wp[tile]
            + (size_t)(colBase + r) * Kd + kOff + seg * 8;
        uint32_t dst = sb + 20480 + tile * 5120 + r * 80 + seg * 16;
        cpa16(dst, src);
    }
}

__global__ __launch_bounds__(256, 1)
void gemm_mma(int layer, const float* __restrict__ bz, const float* __restrict__ bh)
{
    extern __shared__ __align__(16) char sm[];
    const uint32_t sb = s2u(sm);

    const int tid  = threadIdx.x;
    const int lane = tid & 31;
    const int wid  = tid >> 5;
    const int gq   = lane >> 2;      // groupID 0..7
    const int tq   = lane & 3;       // thread in group
    const int wm   = wid & 3;        // warp M block (32 rows)
    const int wn   = wid >> 2;       // warp N block (32 cols)

    const int rowBase = blockIdx.y * 128;
    const int colBase = blockIdx.x * 64;

    const __nv_bfloat16* Wp[4];
#pragma unroll
    for (int i = 0; i < 4; i++) Wp[i] = g_w[4 * layer + i];

    float accZ[2][4][4];
    float accH[2][4][4];
#pragma unroll
    for (int mb = 0; mb < 2; mb++)
#pragma unroll
        for (int nb = 0; nb < 4; nb++)
#pragma unroll
            for (int r = 0; r < 4; r++) { accZ[mb][nb][r] = 0.f; accH[mb][nb][r] = 0.f; }

    // prologue: stages 0..2 for chunks 0..2
#pragma unroll
    for (int s = 0; s < STAGES; s++) {
        load_stage(sb + s * STAGE_BYTES, g_xh, g_xl, Wp, rowBase, colBase, s * KC, tid);
        asm volatile("cp.async.commit_group;" ::: "memory");
    }

    for (int c = 0; c < NCHUNK; c++) {
        if (c <= NCHUNK - 3)      asm volatile("cp.async.wait_group 2;" ::: "memory");
        else if (c == NCHUNK - 2) asm volatile("cp.async.wait_group 1;" ::: "memory");
        else                      asm volatile("cp.async.wait_group 0;" ::: "memory");
        __syncthreads();

        const char* stg = sm + (c % STAGES) * STAGE_BYTES;
        const __nv_bfloat16* sAh  = (const __nv_bfloat16*)(stg);
        const __nv_bfloat16* sAl  = (const __nv_bfloat16*)(stg + 10240);
        const __nv_bfloat16* sWzh = (const __nv_bfloat16*)(stg + 20480);
        const __nv_bfloat16* sWzl = (const __nv_bfloat16*)(stg + 25600);
        const __nv_bfloat16* sWhh = (const __nv_bfloat16*)(stg + 30720);
        const __nv_bfloat16* sWhl = (const __nv_bfloat16*)(stg + 35840);

#pragma unroll
        for (int ks = 0; ks < 2; ks++) {
            const int k0 = ks * 16;
            uint32_t Afh[2][4], Afl[2][4];
#pragma unroll
            for (int mb = 0; mb < 2; mb++) {
                const int r0 = 32 * wm + 16 * mb + gq;
                const int bA = r0 * 40 + k0 + 2 * tq;
                Afh[mb][0] = *(const uint32_t*)(sAh + bA);
                Afh[mb][1] = *(const uint32_t*)(sAh + bA + 320);    // +8 rows
                Afh[mb][2] = *(const uint32_t*)(sAh + bA + 8);      // +8 k
                Afh[mb][3] = *(const uint32_t*)(sAh + bA + 328);
                Afl[mb][0] = *(const uint32_t*)(sAl + bA);
                Afl[mb][1] = *(const uint32_t*)(sAl + bA + 320);
                Afl[mb][2] = *(const uint32_t*)(sAl + bA + 8);
                Afl[mb][3] = *(const uint32_t*)(sAl + bA + 328);
            }
#pragma unroll
            for (int nb = 0; nb < 4; nb++) {
                const int nl = 32 * wn + 8 * nb + gq;
                const int bB = nl * 40 + k0 + 2 * tq;
                uint32_t zh0 = *(const uint32_t*)(sWzh + bB);
                uint32_t zh1 = *(const uint32_t*)(sWzh + bB + 8);
                uint32_t zl0 = *(const uint32_t*)(sWzl + bB);
                uint32_t zl1 = *(const uint32_t*)(sWzl + bB + 8);
                uint32_t hh0 = *(const uint32_t*)(sWhh + bB);
                uint32_t hh1 = *(const uint32_t*)(sWhh + bB + 8);
                uint32_t hl0 = *(const uint32_t*)(sWhl + bB);
                uint32_t hl1 = *(const uint32_t*)(sWhl + bB + 8);
#pragma unroll
                for (int mb = 0; mb < 2; mb++) {
                    mma_bf16(accZ[mb][nb], Afh[mb], zh0, zh1);
                    mma_bf16(accZ[mb][nb], Afl[mb], zh0, zh1);
                    mma_bf16(accZ[mb][nb], Afh[mb], zl0, zl1);
                    mma_bf16(accH[mb][nb], Afh[mb], hh0, hh1);
                    mma_bf16(accH[mb][nb], Afl[mb], hh0, hh1);
                    mma_bf16(accH[mb][nb], Afh[mb], hl0, hl1);
                }
            }
        }

        __syncthreads();
        if (c + STAGES < NCHUNK) {
            load_stage(sb + (c % STAGES) * STAGE_BYTES, g_xh, g_xl, Wp,
                       rowBase, colBase, (c + STAGES) * KC, tid);
            asm volatile("cp.async.commit_group;" ::: "memory");
        }
    }

    // ---------------------- fused activation epilogue ----------------------
#pragma unroll
    for (int mb = 0; mb < 2; mb++) {
        const int r0 = rowBase + 32 * wm + 16 * mb + gq;
#pragma unroll
        for (int nb = 0; nb < 4; nb++) {
            const int col = colBase + 32 * wn + 8 * nb + 2 * tq;
            const float bz0 = bz[col], bz1 = bz[col + 1];
            const float bh0 = bh[col], bh1 = bh[col + 1];
#pragma unroll
            for (int half = 0; half < 2; half++) {
                const int r = r0 + 8 * half;
                const float kv0 = accZ[mb][nb][2 * half]     + bz0;
                const float kv1 = accZ[mb][nb][2 * half + 1] + bz1;
                const float pv0 = accH[mb][nb][2 * half]     + bh0;
                const float pv1 = accH[mb][nb][2 * half + 1] + bh1;
                // a = 1 - sigmoid(k) = sigmoid(-k); b = sigmoid(k)*g(p)
                const float a0 = 1.0f / (1.0f + __expf(kv0));
                const float a1 = 1.0f / (1.0f + __expf(kv1));
                const float z0 = 1.0f / (1.0f + __expf(-kv0));
                const float z1 = 1.0f / (1.0f + __expf(-kv1));
                const float t0 = (pv0 >= 0.f) ? (pv0 + 0.5f)
                                              : (1.0f / (1.0f + __expf(-pv0)));
                const float t1 = (pv1 >= 0.f) ? (pv1 + 0.5f)
                                              : (1.0f / (1.0f + __expf(-pv1)));
                float4 v; v.x = a0; v.y = z0 * t0; v.z = a1; v.w = z1 * t1;
                *(float4*)&g_ab[(size_t)r * Hn + col] = v;
            }
        }
    }
}

// ------------------------------- scan passes --------------------------------
__global__ void scan_pass1()
{
    const int h = threadIdx.x;
    const int c = blockIdx.x;
    const int b = blockIdx.y;
    size_t base = ((size_t)b * Ss + (size_t)c * TLEN) * Hn + h;
    float A = 1.f, Bv = 0.f;
#pragma unroll 8
    for (int t = 0; t < TLEN; t++) {
        float2 ab = g_ab[base + (size_t)t * Hn];
        Bv = fmaf(ab.x, Bv, ab.y);
        A *= ab.x;
    }
    g_cAB[(b * CHUNKS + c) * Hn + h] = make_float2(A, Bv);
}

__global__ void scan_pass2()
{
    const int h = threadIdx.x;
    const int b = blockIdx.x;
    float hv = 0.5f;  // h0 = g(0)
#pragma unroll 16
    for (int c = 0; c < CHUNKS; c++) {
        int idx = (b * CHUNKS + c) * Hn + h;
        g_hs[idx] = hv;
        float2 ab = g_cAB[idx];
        hv = fmaf(ab.x, hv, ab.y);
    }
}

__global__ void scan_pass3(int layer, float* __restrict__ out, float* __restrict__ finalDst)
{
    const int h = threadIdx.x;
    const int c = blockIdx.x;
    const int b = blockIdx.y;
    size_t base = ((size_t)b * Ss + (size_t)c * TLEN) * Hn + h;
    float hv = g_hs[(b * CHUNKS + c) * Hn + h];

    if (layer == 0) {
#pragma unroll 8
        for (int t = 0; t < TLEN; t++) {
            size_t o = base + (size_t)t * Hn;
            float2 ab = g_ab[o];
            hv = fmaf(ab.x, hv, ab.y);
            __nv_bfloat16 hi = __float2bfloat16(hv);
            g_xh[o] = hi;
            g_xl[o] = __float2bfloat16(hv - __bfloat162float(hi));
        }
    } else {
#pragma unroll 8
        for (int t = 0; t < TLEN; t++) {
            size_t o = base + (size_t)t * Hn;
            float2 ab = g_ab[o];
            hv = fmaf(ab.x, hv, ab.y);
            out[o] = hv;
        }
    }
    if (c == CHUNKS - 1)
        finalDst[b * Hn + h] = hv;
}

// --------------------------------- launch ----------------------------------
extern "C" void kernel_launch(void* const* d_in, const int* in_sizes, int n_in,
                              void* d_out, int out_size)
{
    const float* x   = (const float*)d_in[0];
    const float* wz0 = (const float*)d_in[1];
    const float* bz0 = (const float*)d_in[2];
    const float* wh0 = (const float*)d_in[3];
    const float* bh0 = (const float*)d_in[4];
    const float* wz1 = (const float*)d_in[5];
    const float* bz1 = (const float*)d_in[6];
    const float* wh1 = (const float*)d_in[7];
    const float* bh1 = (const float*)d_in[8];

    float* out    = (float*)d_out;
    float* finals = out + (size_t)Mtot * Hn;

    static int smem_set = 0;
    if (!smem_set) {
        cudaFuncSetAttribute(gemm_mma, cudaFuncAttributeMaxDynamicSharedMemorySize,
                             SMEM_BYTES);
        smem_set = 1;
    }

    // conversions
    conv_x_kern<<<(Mtot * Kd / 4) / 256, 256>>>(x);
    conv_w_kern<<<(Kd * Hn / 4) / 256, 256>>>(wz0, 0);
    conv_w_kern<<<(Kd * Hn / 4) / 256, 256>>>(wh0, 2);
    conv_w_kern<<<(Kd * Hn / 4) / 256, 256>>>(wz1, 4);
    conv_w_kern<<<(Kd * Hn / 4) / 256, 256>>>(wh1, 6);

    dim3 gg(Hn / 64, Mtot / 128);    // (8, 256)
    dim3 sg(CHUNKS, Bb);             // (64, 8)

    // layer 0
    gemm_mma<<<gg, 256, SMEM_BYTES>>>(0, bz0, bh0);
    scan_pass1<<<sg, Hn>>>();
    scan_pass2<<<Bb, Hn>>>();
    scan_pass3<<<sg, Hn>>>(0, nullptr, finals);

    // layer 1
    gemm_mma<<<gg, 256, SMEM_BYTES>>>(1, bz1, bh1);
    scan_pass1<<<sg, Hn>>>();
    scan_pass2<<<Bb, Hn>>>();
    scan_pass3<<<sg, Hn>>>(1, out, finals + Bb * Hn);
}

// round 4
// speedup vs baseline: 1.8498x; 1.1622x over previous
#include <cuda_runtime.h>
#include <cuda_bf16.h>
#include <math.h>
#include <stdint.h>

#define Bb 8
#define Ss 4096
#define Hn 512
#define Kd 512
#define Mtot (Bb*Ss)          // 32768

#define CHUNKS2 256
#define TLEN2 (Ss/CHUNKS2)    // 16

// ------------------------- scratch (device globals) -------------------------
__device__ __align__(256) __nv_bfloat16 g_xh[(size_t)Mtot*Kd];
__device__ __align__(256) __nv_bfloat16 g_xl[(size_t)Mtot*Kd];
__device__ __align__(256) float2        g_ab[(size_t)Mtot*Hn];
// lookback state: local (A,B) and inclusive (_, h_end), per layer
__device__ __align__(256) float2        g_loc[2][Bb*CHUNKS2*Hn];
__device__ __align__(256) float2        g_inc[2][Bb*CHUNKS2*Hn];
__device__ __align__(256) int           g_fl [2][Bb*CHUNKS2];
// 0..3: wz0 hi, wz0 lo, wh0 hi, wh0 lo ; 4..7: layer 1
__device__ __align__(256) __nv_bfloat16 g_w[8][(size_t)Kd*Hn];

// ------------------------------ helpers ------------------------------------
__device__ __forceinline__ uint32_t s2u(const void* p) {
    uint32_t a;
    asm("{ .reg .u64 t; cvta.to.shared.u64 t, %1; cvt.u32.u64 %0, t; }"
        : "=r"(a) : "l"(p));
    return a;
}

__device__ __forceinline__ void cpa16(uint32_t dst, const void* src) {
    asm volatile("cp.async.cg.shared.global [%0], [%1], 16;" :: "r"(dst), "l"(src));
}

__device__ __forceinline__ void mma_bf16(float* d, const uint32_t* a,
                                         uint32_t b0, uint32_t b1) {
    asm volatile(
        "mma.sync.aligned.m16n8k16.row.col.f32.bf16.bf16.f32 "
        "{%0,%1,%2,%3}, {%4,%5,%6,%7}, {%8,%9}, {%0,%1,%2,%3};"
        : "+f"(d[0]), "+f"(d[1]), "+f"(d[2]), "+f"(d[3])
        : "r"(a[0]), "r"(a[1]), "r"(a[2]), "r"(a[3]), "r"(b0), "r"(b1));
}

// ------------------------------- conversions -------------------------------
__global__ void clear_flags()
{
    int i = blockIdx.x * blockDim.x + threadIdx.x;
    if (i < 2 * Bb * CHUNKS2) ((int*)g_fl)[i] = 0;
}

__global__ void conv_x_kern(const float* __restrict__ src) {
    int i = blockIdx.x * blockDim.x + threadIdx.x;   // over Mtot*Kd/4
    float4 v = ((const float4*)src)[i];
    __nv_bfloat16 hx = __float2bfloat16(v.x), hy = __float2bfloat16(v.y);
    __nv_bfloat16 hz = __float2bfloat16(v.z), hw = __float2bfloat16(v.w);
    __nv_bfloat16 lx = __float2bfloat16(v.x - __bfloat162float(hx));
    __nv_bfloat16 ly = __float2bfloat16(v.y - __bfloat162float(hy));
    __nv_bfloat16 lz = __float2bfloat16(v.z - __bfloat162float(hz));
    __nv_bfloat16 lw = __float2bfloat16(v.w - __bfloat162float(hw));
    __nv_bfloat162 p0; p0.x = hx; p0.y = hy;
    __nv_bfloat162 p1; p1.x = hz; p1.y = hw;
    __nv_bfloat162 q0; q0.x = lx; q0.y = ly;
    __nv_bfloat162 q1; q1.x = lz; q1.y = lw;
    ((__nv_bfloat162*)g_xh)[2*i  ] = p0;
    ((__nv_bfloat162*)g_xh)[2*i+1] = p1;
    ((__nv_bfloat162*)g_xl)[2*i  ] = q0;
    ((__nv_bfloat162*)g_xl)[2*i+1] = q1;
}

__global__ void conv_w_all(const float* __restrict__ w0, const float* __restrict__ w1,
                           const float* __restrict__ w2, const float* __restrict__ w3) {
    const float* srcs[4] = {w0, w1, w2, w3};
    const int wsel = blockIdx.y;           // 0..3 -> g_w[2*wsel], g_w[2*wsel+1]
    const int widx = 2 * wsel;
    int i = blockIdx.x * blockDim.x + threadIdx.x;   // over Kd*Hn/4
    float4 v = ((const float4*)srcs[wsel])[i];
    __nv_bfloat16 hx = __float2bfloat16(v.x), hy = __float2bfloat16(v.y);
    __nv_bfloat16 hz = __float2bfloat16(v.z), hw = __float2bfloat16(v.w);
    __nv_bfloat16 lx = __float2bfloat16(v.x - __bfloat162float(hx));
    __nv_bfloat16 ly = __float2bfloat16(v.y - __bfloat162float(hy));
    __nv_bfloat16 lz = __float2bfloat16(v.z - __bfloat162float(hz));
    __nv_bfloat16 lw = __float2bfloat16(v.w - __bfloat162float(hw));
    __nv_bfloat162 p0; p0.x = hx; p0.y = hy;
    __nv_bfloat162 p1; p1.x = hz; p1.y = hw;
    __nv_bfloat162 q0; q0.x = lx; q0.y = ly;
    __nv_bfloat162 q1; q1.x = lz; q1.y = lw;
    ((__nv_bfloat162*)g_w[widx    ])[2*i  ] = p0;
    ((__nv_bfloat162*)g_w[widx    ])[2*i+1] = p1;
    ((__nv_bfloat162*)g_w[widx + 1])[2*i  ] = q0;
    ((__nv_bfloat162*)g_w[widx + 1])[2*i+1] = q1;
}

// --------------------------- mma.sync dual GEMM -----------------------------
// CTA tile: 128 M x 64 N, Z and H accumulators. 2-stage cp.async, KC=32,
// 2 CTAs / SM. smem per stage: AH 0, AL 10240, WZH 20480, WZL 25600,
// WHH 30720, WHL 35840. Row stride 40 bf16 (80B).
#define KC 32
#define STAGES 2
#define STAGE_BYTES 40960
#define SMEM_BYTES (STAGES*STAGE_BYTES)
#define NCHUNK (Kd/KC)   // 16

__device__ __forceinline__ void load_stage(uint32_t sb,
    const __nv_bfloat16* Ah, const __nv_bfloat16* Al,
    const __nv_bfloat16* const* Wp,
    int rowBase, int colBase, int kOff, int tid)
{
#pragma unroll
    for (int i = 0; i < 4; i++) {
        int idx  = tid + i * 256;        // 0..1023
        int tile = idx >> 9;             // 0=hi, 1=lo
        int r    = (idx >> 2) & 127;
        int seg  = idx & 3;
        const __nv_bfloat16* src = (tile ? Al : Ah)
            + (size_t)(rowBase + r) * Kd + kOff + seg * 8;
        uint32_t dst = sb + tile * 10240 + r * 80 + seg * 16;
        cpa16(dst, src);
    }
#pragma unroll
    for (int i = 0; i < 4; i++) {
        int idx  = tid + i * 256;        // 0..1023
        int tile = idx >> 8;             // 0..3
        int r    = (idx >> 2) & 63;
        int seg  = idx & 3;
        const __nv_bfloat16* src = Wp[tile]
            + (size_t)(colBase + r) * Kd + kOff + seg * 8;
        uint32_t dst = sb + 20480 + tile * 5120 + r * 80 + seg * 16;
        cpa16(dst, src);
    }
}

__global__ __launch_bounds__(256, 2)
void gemm_mma(int layer, const float* __restrict__ bz, const float* __restrict__ bh)
{
    extern __shared__ __align__(16) char sm[];
    const uint32_t sb = s2u(sm);

    const int tid  = threadIdx.x;
    const int lane = tid & 31;
    const int wid  = tid >> 5;
    const int gq   = lane >> 2;      // groupID 0..7
    const int tq   = lane & 3;       // thread in group
    const int wm   = wid & 3;        // warp M block (32 rows)
    const int wn   = wid >> 2;       // warp N block (32 cols)

    const int rowBase = blockIdx.y * 128;
    const int colBase = blockIdx.x * 64;

    const __nv_bfloat16* Wp[4];
#pragma unroll
    for (int i = 0; i < 4; i++) Wp[i] = g_w[4 * layer + i];

    float accZ[2][4][4];
    float accH[2][4][4];
#pragma unroll
    for (int mb = 0; mb < 2; mb++)
#pragma unroll
        for (int nb = 0; nb < 4; nb++)
#pragma unroll
            for (int r = 0; r < 4; r++) { accZ[mb][nb][r] = 0.f; accH[mb][nb][r] = 0.f; }

    // prologue: stages 0,1 for chunks 0,1
#pragma unroll
    for (int s = 0; s < STAGES; s++) {
        load_stage(sb + s * STAGE_BYTES, g_xh, g_xl, Wp, rowBase, colBase, s * KC, tid);
        asm volatile("cp.async.commit_group;" ::: "memory");
    }

    for (int c = 0; c < NCHUNK; c++) {
        if (c < NCHUNK - 1) asm volatile("cp.async.wait_group 1;" ::: "memory");
        else                asm volatile("cp.async.wait_group 0;" ::: "memory");
        __syncthreads();

        const char* stg = sm + (c % STAGES) * STAGE_BYTES;
        const __nv_bfloat16* sAh  = (const __nv_bfloat16*)(stg);
        const __nv_bfloat16* sAl  = (const __nv_bfloat16*)(stg + 10240);
        const __nv_bfloat16* sWzh = (const __nv_bfloat16*)(stg + 20480);
        const __nv_bfloat16* sWzl = (const __nv_bfloat16*)(stg + 25600);
        const __nv_bfloat16* sWhh = (const __nv_bfloat16*)(stg + 30720);
        const __nv_bfloat16* sWhl = (const __nv_bfloat16*)(stg + 35840);

#pragma unroll
        for (int ks = 0; ks < 2; ks++) {
            const int k0 = ks * 16;
            uint32_t Afh[2][4], Afl[2][4];
#pragma unroll
            for (int mb = 0; mb < 2; mb++) {
                const int r0 = 32 * wm + 16 * mb + gq;
                const int bA = r0 * 40 + k0 + 2 * tq;
                Afh[mb][0] = *(const uint32_t*)(sAh + bA);
                Afh[mb][1] = *(const uint32_t*)(sAh + bA + 320);    // +8 rows
                Afh[mb][2] = *(const uint32_t*)(sAh + bA + 8);      // +8 k
                Afh[mb][3] = *(const uint32_t*)(sAh + bA + 328);
                Afl[mb][0] = *(const uint32_t*)(sAl + bA);
                Afl[mb][1] = *(const uint32_t*)(sAl + bA + 320);
                Afl[mb][2] = *(const uint32_t*)(sAl + bA + 8);
                Afl[mb][3] = *(const uint32_t*)(sAl + bA + 328);
            }
#pragma unroll
            for (int nb = 0; nb < 4; nb++) {
                const int nl = 32 * wn + 8 * nb + gq;
                const int bB = nl * 40 + k0 + 2 * tq;
                uint32_t zh0 = *(const uint32_t*)(sWzh + bB);
                uint32_t zh1 = *(const uint32_t*)(sWzh + bB + 8);
                uint32_t zl0 = *(const uint32_t*)(sWzl + bB);
                uint32_t zl1 = *(const uint32_t*)(sWzl + bB + 8);
                uint32_t hh0 = *(const uint32_t*)(sWhh + bB);
                uint32_t hh1 = *(const uint32_t*)(sWhh + bB + 8);
                uint32_t hl0 = *(const uint32_t*)(sWhl + bB);
                uint32_t hl1 = *(const uint32_t*)(sWhl + bB + 8);
#pragma unroll
                for (int mb = 0; mb < 2; mb++) {
                    mma_bf16(accZ[mb][nb], Afh[mb], zh0, zh1);
                    mma_bf16(accZ[mb][nb], Afl[mb], zh0, zh1);
                    mma_bf16(accZ[mb][nb], Afh[mb], zl0, zl1);
                    mma_bf16(accH[mb][nb], Afh[mb], hh0, hh1);
                    mma_bf16(accH[mb][nb], Afl[mb], hh0, hh1);
                    mma_bf16(accH[mb][nb], Afh[mb], hl0, hl1);
                }
            }
        }

        __syncthreads();
        if (c + STAGES < NCHUNK) {
            load_stage(sb + (c % STAGES) * STAGE_BYTES, g_xh, g_xl, Wp,
                       rowBase, colBase, (c + STAGES) * KC, tid);
            asm volatile("cp.async.commit_group;" ::: "memory");
        }
    }

    // ---------------------- fused activation epilogue ----------------------
#pragma unroll
    for (int mb = 0; mb < 2; mb++) {
        const int r0 = rowBase + 32 * wm + 16 * mb + gq;
#pragma unroll
        for (int nb = 0; nb < 4; nb++) {
            const int col = colBase + 32 * wn + 8 * nb + 2 * tq;
            const float bz0 = bz[col], bz1 = bz[col + 1];
            const float bh0 = bh[col], bh1 = bh[col + 1];
#pragma unroll
            for (int half = 0; half < 2; half++) {
                const int r = r0 + 8 * half;
                const float kv0 = accZ[mb][nb][2 * half]     + bz0;
                const float kv1 = accZ[mb][nb][2 * half + 1] + bz1;
                const float pv0 = accH[mb][nb][2 * half]     + bh0;
                const float pv1 = accH[mb][nb][2 * half + 1] + bh1;
                const float a0 = 1.0f / (1.0f + __expf(kv0));
                const float a1 = 1.0f / (1.0f + __expf(kv1));
                const float z0 = 1.0f / (1.0f + __expf(-kv0));
                const float z1 = 1.0f / (1.0f + __expf(-kv1));
                const float t0 = (pv0 >= 0.f) ? (pv0 + 0.5f)
                                              : (1.0f / (1.0f + __expf(-pv0)));
                const float t1 = (pv1 >= 0.f) ? (pv1 + 0.5f)
                                              : (1.0f / (1.0f + __expf(-pv1)));
                float4 v; v.x = a0; v.y = z0 * t0; v.z = a1; v.w = z1 * t1;
                *(float4*)&g_ab[(size_t)r * Hn + col] = v;
            }
        }
    }
}

// ------------------ single-pass scan with decoupled lookback ----------------
// grid (CHUNKS2=256, Bb), block 512 (h = tid). Each thread holds its chunk's
// 16 (a,b) pairs in registers, publishes local (A,B), looks back composing
// predecessor locals until an inclusive h is found, publishes inclusive,
// then emits the hidden sequence from registers.
__global__ __launch_bounds__(512)
void scan_fused(int layer, float* __restrict__ out, float* __restrict__ finalDst)
{
    const int h = threadIdx.x;
    const int c = blockIdx.x;
    const int b = blockIdx.y;
    const size_t base = ((size_t)b * Ss + (size_t)c * TLEN2) * Hn + h;

    float2 v[TLEN2];
#pragma unroll
    for (int t = 0; t < TLEN2; t++)
        v[t] = g_ab[base + (size_t)t * Hn];

    float A = 1.f, Bv = 0.f;
#pragma unroll
    for (int t = 0; t < TLEN2; t++) {
        Bv = fmaf(v[t].x, Bv, v[t].y);
        A *= v[t].x;
    }

    const int cidx = b * CHUNKS2 + c;
    __shared__ int s_st;
    float hstart;

    if (c == 0) {
        hstart = 0.5f;   // h0 = g(0)
        float2 pub; pub.x = 0.f; pub.y = fmaf(A, hstart, Bv);
        __stcg(&g_inc[layer][(size_t)cidx * Hn + h], pub);
        __threadfence();
        __syncthreads();
        if (h == 0) atomicExch(&g_fl[layer][cidx], 2);
    } else {
        float2 pub; pub.x = A; pub.y = Bv;
        __stcg(&g_loc[layer][(size_t)cidx * Hn + h], pub);
        __threadfence();
        __syncthreads();
        if (h == 0) atomicExch(&g_fl[layer][cidx], 1);

        float alpha = 1.f, beta = 0.f;
        int p = c - 1;
        for (;;) {
            const int pidx = b * CHUNKS2 + p;
            if (h == 0) {
                int f;
                do { f = atomicAdd(&g_fl[layer][pidx], 0); } while (f == 0);
                s_st = f;
            }
            __syncthreads();
            const int stf = s_st;
            __syncthreads();
            if (stf == 2) {
                float2 pv = __ldcg(&g_inc[layer][(size_t)pidx * Hn + h]);
                hstart = fmaf(alpha, pv.y, beta);
                break;
            } else {
                float2 pv = __ldcg(&g_loc[layer][(size_t)pidx * Hn + h]);
                beta  = fmaf(alpha, pv.y, beta);
                alpha *= pv.x;
                p--;
            }
        }

        float2 pub2; pub2.x = 0.f; pub2.y = fmaf(A, hstart, Bv);
        __stcg(&g_inc[layer][(size_t)cidx * Hn + h], pub2);
        __threadfence();
        __syncthreads();
        if (h == 0) atomicExch(&g_fl[layer][cidx], 2);
    }

    // emit hidden sequence from registers
    float hv = hstart;
    if (layer == 0) {
#pragma unroll
        for (int t = 0; t < TLEN2; t++) {
            hv = fmaf(v[t].x, hv, v[t].y);
            size_t o = base + (size_t)t * Hn;
            __nv_bfloat16 hi = __float2bfloat16(hv);
            g_xh[o] = hi;
            g_xl[o] = __float2bfloat16(hv - __bfloat162float(hi));
        }
    } else {
#pragma unroll
        for (int t = 0; t < TLEN2; t++) {
            hv = fmaf(v[t].x, hv, v[t].y);
            out[base + (size_t)t * Hn] = hv;
        }
    }
    if (c == CHUNKS2 - 1)
        finalDst[b * Hn + h] = hv;
}

// --------------------------------- launch ----------------------------------
extern "C" void kernel_launch(void* const* d_in, const int* in_sizes, int n_in,
                              void* d_out, int out_size)
{
    const float* x   = (const float*)d_in[0];
    const float* wz0 = (const float*)d_in[1];
    const float* bz0 = (const float*)d_in[2];
    const float* wh0 = (const float*)d_in[3];
    const float* bh0 = (const float*)d_in[4];
    const float* wz1 = (const float*)d_in[5];
    const float* bz1 = (const float*)d_in[6];
    const float* wh1 = (const float*)d_in[7];
    const float* bh1 = (const float*)d_in[8];

    float* out    = (float*)d_out;
    float* finals = out + (size_t)Mtot * Hn;

    static int smem_set = 0;
    if (!smem_set) {
        cudaFuncSetAttribute(gemm_mma, cudaFuncAttributeMaxDynamicSharedMemorySize,
                             SMEM_BYTES);
        smem_set = 1;
    }

    clear_flags<<<(2 * Bb * CHUNKS2 + 255) / 256, 256>>>();
    conv_x_kern<<<(Mtot * Kd / 4) / 256, 256>>>(x);
    conv_w_all<<<dim3((Kd * Hn / 4) / 256, 4), 256>>>(wz0, wh0, wz1, wh1);

    dim3 gg(Hn / 64, Mtot / 128);    // (8, 256)
    dim3 sg(CHUNKS2, Bb);            // (256, 8)

    // layer 0
    gemm_mma<<<gg, 256, SMEM_BYTES>>>(0, bz0, bh0);
    scan_fused<<<sg, Hn>>>(0, nullptr, finals);

    // layer 1
    gemm_mma<<<gg, 256, SMEM_BYTES>>>(1, bz1, bh1);
    scan_fused<<<sg, Hn>>>(1, out, finals + Bb * Hn);
}

// round 5
// speedup vs baseline: 1.9090x; 1.0320x over previous
#include <cuda_runtime.h>
#include <cuda_bf16.h>
#include <math.h>
#include <stdint.h>

#define Bb 8
#define Ss 4096
#define Hn 512
#define Kd 512
#define Mtot (Bb*Ss)          // 32768

#define CHUNKS2 256
#define TLEN2 (Ss/CHUNKS2)    // 16

// ------------------------- scratch (device globals) -------------------------
__device__ __align__(256) __nv_bfloat16 g_xh[(size_t)Mtot*Kd];
__device__ __align__(256) __nv_bfloat16 g_xl[(size_t)Mtot*Kd];
__device__ __align__(256) float2        g_ab[(size_t)Mtot*Hn];
__device__ __align__(256) float2        g_loc[2][Bb*CHUNKS2*Hn];
__device__ __align__(256) float2        g_inc[2][Bb*CHUNKS2*Hn];
__device__ __align__(256) int           g_fl [2][Bb*CHUNKS2];
// 0..3: wz0 hi, wz0 lo, wh0 hi, wh0 lo ; 4..7: layer 1
__device__ __align__(256) __nv_bfloat16 g_w[8][(size_t)Kd*Hn];

// ------------------------------ helpers ------------------------------------
__device__ __forceinline__ uint32_t s2u(const void* p) {
    uint32_t a;
    asm("{ .reg .u64 t; cvta.to.shared.u64 t, %1; cvt.u32.u64 %0, t; }"
        : "=r"(a) : "l"(p));
    return a;
}

__device__ __forceinline__ void cpa16(uint32_t dst, const void* src) {
    asm volatile("cp.async.cg.shared.global [%0], [%1], 16;" :: "r"(dst), "l"(src));
}

__device__ __forceinline__ void mma_bf16(float* d, const uint32_t* a,
                                         uint32_t b0, uint32_t b1) {
    asm volatile(
        "mma.sync.aligned.m16n8k16.row.col.f32.bf16.bf16.f32 "
        "{%0,%1,%2,%3}, {%4,%5,%6,%7}, {%8,%9}, {%0,%1,%2,%3};"
        : "+f"(d[0]), "+f"(d[1]), "+f"(d[2]), "+f"(d[3])
        : "r"(a[0]), "r"(a[1]), "r"(a[2]), "r"(a[3]), "r"(b0), "r"(b1));
}

__device__ __forceinline__ void ldsm4(uint32_t* r, uint32_t addr) {
    asm volatile("ldmatrix.sync.aligned.m8n8.x4.shared.b16 {%0,%1,%2,%3}, [%4];"
        : "=r"(r[0]), "=r"(r[1]), "=r"(r[2]), "=r"(r[3]) : "r"(addr));
}

// ------------------------------- conversions -------------------------------
__global__ void clear_flags()
{
    int i = blockIdx.x * blockDim.x + threadIdx.x;
    if (i < 2 * Bb * CHUNKS2) ((int*)g_fl)[i] = 0;
}

__global__ void conv_x_kern(const float* __restrict__ src) {
    int i = blockIdx.x * blockDim.x + threadIdx.x;   // over Mtot*Kd/4
    float4 v = ((const float4*)src)[i];
    __nv_bfloat16 hx = __float2bfloat16(v.x), hy = __float2bfloat16(v.y);
    __nv_bfloat16 hz = __float2bfloat16(v.z), hw = __float2bfloat16(v.w);
    __nv_bfloat16 lx = __float2bfloat16(v.x - __bfloat162float(hx));
    __nv_bfloat16 ly = __float2bfloat16(v.y - __bfloat162float(hy));
    __nv_bfloat16 lz = __float2bfloat16(v.z - __bfloat162float(hz));
    __nv_bfloat16 lw = __float2bfloat16(v.w - __bfloat162float(hw));
    __nv_bfloat162 p0; p0.x = hx; p0.y = hy;
    __nv_bfloat162 p1; p1.x = hz; p1.y = hw;
    __nv_bfloat162 q0; q0.x = lx; q0.y = ly;
    __nv_bfloat162 q1; q1.x = lz; q1.y = lw;
    ((__nv_bfloat162*)g_xh)[2*i  ] = p0;
    ((__nv_bfloat162*)g_xh)[2*i+1] = p1;
    ((__nv_bfloat162*)g_xl)[2*i  ] = q0;
    ((__nv_bfloat162*)g_xl)[2*i+1] = q1;
}

__global__ void conv_w_all(const float* __restrict__ w0, const float* __restrict__ w1,
                           const float* __restrict__ w2, const float* __restrict__ w3) {
    const float* srcs[4] = {w0, w1, w2, w3};
    const int wsel = blockIdx.y;
    const int widx = 2 * wsel;
    int i = blockIdx.x * blockDim.x + threadIdx.x;   // over Kd*Hn/4
    float4 v = ((const float4*)srcs[wsel])[i];
    __nv_bfloat16 hx = __float2bfloat16(v.x), hy = __float2bfloat16(v.y);
    __nv_bfloat16 hz = __float2bfloat16(v.z), hw = __float2bfloat16(v.w);
    __nv_bfloat16 lx = __float2bfloat16(v.x - __bfloat162float(hx));
    __nv_bfloat16 ly = __float2bfloat16(v.y - __bfloat162float(hy));
    __nv_bfloat16 lz = __float2bfloat16(v.z - __bfloat162float(hz));
    __nv_bfloat16 lw = __float2bfloat16(v.w - __bfloat162float(hw));
    __nv_bfloat162 p0; p0.x = hx; p0.y = hy;
    __nv_bfloat162 p1; p1.x = hz; p1.y = hw;
    __nv_bfloat162 q0; q0.x = lx; q0.y = ly;
    __nv_bfloat162 q1; q1.x = lz; q1.y = lw;
    ((__nv_bfloat162*)g_w[widx    ])[2*i  ] = p0;
    ((__nv_bfloat162*)g_w[widx    ])[2*i+1] = p1;
    ((__nv_bfloat162*)g_w[widx + 1])[2*i  ] = q0;
    ((__nv_bfloat162*)g_w[widx + 1])[2*i+1] = q1;
}

// --------------------------- mma.sync dual GEMM -----------------------------
// CTA tile 128M x 64N; Z and H accumulators; 2-stage cp.async; 2 CTAs/SM.
// smem per stage: AH 0, AL 10240, WZH 20480, WZL 25600, WHH 30720, WHL 35840.
// Row stride 40 bf16 (80B) — ldmatrix conflict-free (80B*r mod 128B partitions banks).
#define KC 32
#define STAGES 2
#define STAGE_BYTES 40960
#define SMEM_BYTES (STAGES*STAGE_BYTES)
#define NCHUNK (Kd/KC)   // 16

__device__ __forceinline__ void load_stage(uint32_t sb,
    const __nv_bfloat16* Ah, const __nv_bfloat16* Al,
    const __nv_bfloat16* const* Wp,
    int rowBase, int colBase, int kOff, int tid)
{
#pragma unroll
    for (int i = 0; i < 4; i++) {
        int idx  = tid + i * 256;        // 0..1023
        int tile = idx >> 9;             // 0=hi, 1=lo
        int r    = (idx >> 2) & 127;
        int seg  = idx & 3;
        const __nv_bfloat16* src = (tile ? Al : Ah)
            + (size_t)(rowBase + r) * Kd + kOff + seg * 8;
        uint32_t dst = sb + tile * 10240 + r * 80 + seg * 16;
        cpa16(dst, src);
    }
#pragma unroll
    for (int i = 0; i < 4; i++) {
        int idx  = tid + i * 256;        // 0..1023
        int tile = idx >> 8;             // 0..3
        int r    = (idx >> 2) & 63;
        int seg  = idx & 3;
        const __nv_bfloat16* src = Wp[tile]
            + (size_t)(colBase + r) * Kd + kOff + seg * 8;
        uint32_t dst = sb + 20480 + tile * 5120 + r * 80 + seg * 16;
        cpa16(dst, src);
    }
}

__global__ __launch_bounds__(256, 2)
void gemm_mma(int layer, const float* __restrict__ bz, const float* __restrict__ bh)
{
    extern __shared__ __align__(16) char sm[];
    const uint32_t sb = s2u(sm);

    const int tid  = threadIdx.x;
    const int lane = tid & 31;
    const int wid  = tid >> 5;
    const int gq   = lane >> 2;
    const int tq   = lane & 3;
    const int wm   = wid & 3;        // warp M block (32 rows)
    const int wn   = wid >> 2;       // warp N block (32 cols)

    const int rowBase = blockIdx.y * 128;
    const int colBase = blockIdx.x * 64;

    const __nv_bfloat16* Wp[4];
#pragma unroll
    for (int i = 0; i < 4; i++) Wp[i] = g_w[4 * layer + i];

    // ldmatrix lane offsets (bytes), relative to tile base in a stage
    // A (m16k16 x4): row = lane&15 within 16-row block, k half = lane>>4
    const uint32_t aLane = (uint32_t)((32 * wm + (lane & 15)) * 80 + ((lane >> 4) << 4));
    // B (two n8 blocks x4): n = 16*pair + ((lane>>4)<<3) + (lane&7), k half = (lane>>3)&1
    const uint32_t bLane = (uint32_t)(((32 * wn) + ((lane >> 4) << 3) + (lane & 7)) * 80
                                      + (((lane >> 3) & 1) << 4));

    float accZ[2][4][4];
    float accH[2][4][4];
#pragma unroll
    for (int mb = 0; mb < 2; mb++)
#pragma unroll
        for (int nb = 0; nb < 4; nb++)
#pragma unroll
            for (int r = 0; r < 4; r++) { accZ[mb][nb][r] = 0.f; accH[mb][nb][r] = 0.f; }

#pragma unroll
    for (int s = 0; s < STAGES; s++) {
        load_stage(sb + s * STAGE_BYTES, g_xh, g_xl, Wp, rowBase, colBase, s * KC, tid);
        asm volatile("cp.async.commit_group;" ::: "memory");
    }

    for (int c = 0; c < NCHUNK; c++) {
        if (c < NCHUNK - 1) asm volatile("cp.async.wait_group 1;" ::: "memory");
        else                asm volatile("cp.async.wait_group 0;" ::: "memory");
        __syncthreads();

        const uint32_t stg = sb + (c % STAGES) * STAGE_BYTES;
        const uint32_t aH = stg +     0 + aLane;
        const uint32_t aL = stg + 10240 + aLane;
        const uint32_t bZH = stg + 20480 + bLane;
        const uint32_t bZL = stg + 25600 + bLane;
        const uint32_t bHH = stg + 30720 + bLane;
        const uint32_t bHL = stg + 35840 + bLane;

#pragma unroll
        for (int ks = 0; ks < 2; ks++) {
            const uint32_t kb = (uint32_t)(ks * 32);   // 16 bf16 = 32 bytes
            uint32_t Afh[2][4], Afl[2][4];
#pragma unroll
            for (int mb = 0; mb < 2; mb++) {
                ldsm4(Afh[mb], aH + mb * (16 * 80) + kb);
                ldsm4(Afl[mb], aL + mb * (16 * 80) + kb);
            }
#pragma unroll
            for (int p = 0; p < 2; p++) {
                const uint32_t po = (uint32_t)(p * (16 * 80)) + kb;
                uint32_t zh[4], zl[4], hh[4], hl[4];
                ldsm4(zh, bZH + po);
                ldsm4(zl, bZL + po);
                ldsm4(hh, bHH + po);
                ldsm4(hl, bHL + po);
#pragma unroll
                for (int q = 0; q < 2; q++) {
                    const int nb = 2 * p + q;
#pragma unroll
                    for (int mb = 0; mb < 2; mb++) {
                        mma_bf16(accZ[mb][nb], Afh[mb], zh[2*q], zh[2*q+1]);
                        mma_bf16(accZ[mb][nb], Afl[mb], zh[2*q], zh[2*q+1]);
                        mma_bf16(accZ[mb][nb], Afh[mb], zl[2*q], zl[2*q+1]);
                        mma_bf16(accH[mb][nb], Afh[mb], hh[2*q], hh[2*q+1]);
                        mma_bf16(accH[mb][nb], Afl[mb], hh[2*q], hh[2*q+1]);
                        mma_bf16(accH[mb][nb], Afh[mb], hl[2*q], hl[2*q+1]);
                    }
                }
            }
        }

        __syncthreads();
        if (c + STAGES < NCHUNK) {
            load_stage(sb + (c % STAGES) * STAGE_BYTES, g_xh, g_xl, Wp,
                       rowBase, colBase, (c + STAGES) * KC, tid);
            asm volatile("cp.async.commit_group;" ::: "memory");
        }
    }

    // ---------------------- fused activation epilogue ----------------------
#pragma unroll
    for (int mb = 0; mb < 2; mb++) {
        const int r0 = rowBase + 32 * wm + 16 * mb + gq;
#pragma unroll
        for (int nb = 0; nb < 4; nb++) {
            const int col = colBase + 32 * wn + 8 * nb + 2 * tq;
            const float bz0 = bz[col], bz1 = bz[col + 1];
            const float bh0 = bh[col], bh1 = bh[col + 1];
#pragma unroll
            for (int half = 0; half < 2; half++) {
                const int r = r0 + 8 * half;
                const float kv0 = accZ[mb][nb][2 * half]     + bz0;
                const float kv1 = accZ[mb][nb][2 * half + 1] + bz1;
                const float pv0 = accH[mb][nb][2 * half]     + bh0;
                const float pv1 = accH[mb][nb][2 * half + 1] + bh1;
                const float a0 = 1.0f / (1.0f + __expf(kv0));
                const float a1 = 1.0f / (1.0f + __expf(kv1));
                const float z0 = 1.0f / (1.0f + __expf(-kv0));
                const float z1 = 1.0f / (1.0f + __expf(-kv1));
                const float t0 = (pv0 >= 0.f) ? (pv0 + 0.5f)
                                              : (1.0f / (1.0f + __expf(-pv0)));
                const float t1 = (pv1 >= 0.f) ? (pv1 + 0.5f)
                                              : (1.0f / (1.0f + __expf(-pv1)));
                float4 v; v.x = a0; v.y = z0 * t0; v.z = a1; v.w = z1 * t1;
                *(float4*)&g_ab[(size_t)r * Hn + col] = v;
            }
        }
    }
}

// ------------------ single-pass scan with decoupled lookback ----------------
__global__ __launch_bounds__(512)
void scan_fused(int layer, float* __restrict__ out, float* __restrict__ finalDst)
{
    const int h = threadIdx.x;
    const int c = blockIdx.x;
    const int b = blockIdx.y;
    const size_t base = ((size_t)b * Ss + (size_t)c * TLEN2) * Hn + h;

    float2 v[TLEN2];
#pragma unroll
    for (int t = 0; t < TLEN2; t++)
        v[t] = g_ab[base + (size_t)t * Hn];

    float A = 1.f, Bv = 0.f;
#pragma unroll
    for (int t = 0; t < TLEN2; t++) {
        Bv = fmaf(v[t].x, Bv, v[t].y);
        A *= v[t].x;
    }

    const int cidx = b * CHUNKS2 + c;
    __shared__ int s_st;
    float hstart;

    if (c == 0) {
        hstart = 0.5f;
        float2 pub; pub.x = 0.f; pub.y = fmaf(A, hstart, Bv);
        __stcg(&g_inc[layer][(size_t)cidx * Hn + h], pub);
        __threadfence();
        __syncthreads();
        if (h == 0) atomicExch(&g_fl[layer][cidx], 2);
    } else {
        float2 pub; pub.x = A; pub.y = Bv;
        __stcg(&g_loc[layer][(size_t)cidx * Hn + h], pub);
        __threadfence();
        __syncthreads();
        if (h == 0) atomicExch(&g_fl[layer][cidx], 1);

        float alpha = 1.f, beta = 0.f;
        int p = c - 1;
        for (;;) {
            const int pidx = b * CHUNKS2 + p;
            if (h == 0) {
                int f;
                do { f = atomicAdd(&g_fl[layer][pidx], 0); } while (f == 0);
                s_st = f;
            }
            __syncthreads();
            const int stf = s_st;
            __syncthreads();
            if (stf == 2) {
                float2 pv = __ldcg(&g_inc[layer][(size_t)pidx * Hn + h]);
                hstart = fmaf(alpha, pv.y, beta);
                break;
            } else {
                float2 pv = __ldcg(&g_loc[layer][(size_t)pidx * Hn + h]);
                beta  = fmaf(alpha, pv.y, beta);
                alpha *= pv.x;
                p--;
            }
        }

        float2 pub2; pub2.x = 0.f; pub2.y = fmaf(A, hstart, Bv);
        __stcg(&g_inc[layer][(size_t)cidx * Hn + h], pub2);
        __threadfence();
        __syncthreads();
        if (h == 0) atomicExch(&g_fl[layer][cidx], 2);
    }

    float hv = hstart;
    if (layer == 0) {
#pragma unroll
        for (int t = 0; t < TLEN2; t++) {
            hv = fmaf(v[t].x, hv, v[t].y);
            size_t o = base + (size_t)t * Hn;
            __nv_bfloat16 hi = __float2bfloat16(hv);
            g_xh[o] = hi;
            g_xl[o] = __float2bfloat16(hv - __bfloat162float(hi));
        }
    } else {
#pragma unroll
        for (int t = 0; t < TLEN2; t++) {
            hv = fmaf(v[t].x, hv, v[t].y);
            out[base + (size_t)t * Hn] = hv;
        }
    }
    if (c == CHUNKS2 - 1)
        finalDst[b * Hn + h] = hv;
}

// --------------------------------- launch ----------------------------------
extern "C" void kernel_launch(void* const* d_in, const int* in_sizes, int n_in,
                              void* d_out, int out_size)
{
    const float* x   = (const float*)d_in[0];
    const float* wz0 = (const float*)d_in[1];
    const float* bz0 = (const float*)d_in[2];
    const float* wh0 = (const float*)d_in[3];
    const float* bh0 = (const float*)d_in[4];
    const float* wz1 = (const float*)d_in[5];
    const float* bz1 = (const float*)d_in[6];
    const float* wh1 = (const float*)d_in[7];
    const float* bh1 = (const float*)d_in[8];

    float* out    = (float*)d_out;
    float* finals = out + (size_t)Mtot * Hn;

    static int smem_set = 0;
    if (!smem_set) {
        cudaFuncSetAttribute(gemm_mma, cudaFuncAttributeMaxDynamicSharedMemorySize,
                             SMEM_BYTES);
        smem_set = 1;
    }

    clear_flags<<<(2 * Bb * CHUNKS2 + 255) / 256, 256>>>();
    conv_x_kern<<<(Mtot * Kd / 4) / 256, 256>>>(x);
    conv_w_all<<<dim3((Kd * Hn / 4) / 256, 4), 256>>>(wz0, wh0, wz1, wh1);

    dim3 gg(Hn / 64, Mtot / 128);    // (8, 256)
    dim3 sg(CHUNKS2, Bb);            // (256, 8)

    gemm_mma<<<gg, 256, SMEM_BYTES>>>(0, bz0, bh0);
    scan_fused<<<sg, Hn>>>(0, nullptr, finals);

    gemm_mma<<<gg, 256, SMEM_BYTES>>>(1, bz1, bh1);
    scan_fused<<<sg, Hn>>>(1, out, finals + Bb * Hn);
}

// round 6
// speedup vs baseline: 2.3500x; 1.2310x over previous
#include <cuda_runtime.h>
#include <cuda_fp16.h>
#include <math.h>
#include <stdint.h>

#define Bb 8
#define Ss 4096
#define Hn 512
#define Kd 512
#define Mtot (Bb*Ss)          // 32768

#define CHUNKS2 256
#define TLEN2 (Ss/CHUNKS2)    // 16

// ------------------------- scratch (device globals) -------------------------
__device__ __align__(256) __half  g_xh[(size_t)Mtot*Kd];
__device__ __align__(256) __half  g_xl[(size_t)Mtot*Kd];
__device__ __align__(256) float2  g_ab[(size_t)Mtot*Hn];
__device__ __align__(256) float2  g_loc[2][Bb*CHUNKS2*Hn];
__device__ __align__(256) float2  g_inc[2][Bb*CHUNKS2*Hn];
__device__ __align__(256) int     g_fl [2][Bb*CHUNKS2];
// 0: wz0, 1: wh0, 2: wz1, 3: wh1 (fp16 hi only)
__device__ __align__(256) __half  g_w[4][(size_t)Kd*Hn];

// ------------------------------ helpers ------------------------------------
__device__ __forceinline__ uint32_t s2u(const void* p) {
    uint32_t a;
    asm("{ .reg .u64 t; cvta.to.shared.u64 t, %1; cvt.u32.u64 %0, t; }"
        : "=r"(a) : "l"(p));
    return a;
}

__device__ __forceinline__ void cpa16(uint32_t dst, const void* src) {
    asm volatile("cp.async.cg.shared.global [%0], [%1], 16;" :: "r"(dst), "l"(src));
}

__device__ __forceinline__ void mma_f16(float* d, const uint32_t* a,
                                        uint32_t b0, uint32_t b1) {
    asm volatile(
        "mma.sync.aligned.m16n8k16.row.col.f32.f16.f16.f32 "
        "{%0,%1,%2,%3}, {%4,%5,%6,%7}, {%8,%9}, {%0,%1,%2,%3};"
        : "+f"(d[0]), "+f"(d[1]), "+f"(d[2]), "+f"(d[3])
        : "r"(a[0]), "r"(a[1]), "r"(a[2]), "r"(a[3]), "r"(b0), "r"(b1));
}

__device__ __forceinline__ void ldsm4(uint32_t* r, uint32_t addr) {
    asm volatile("ldmatrix.sync.aligned.m8n8.x4.shared.b16 {%0,%1,%2,%3}, [%4];"
        : "=r"(r[0]), "=r"(r[1]), "=r"(r[2]), "=r"(r[3]) : "r"(addr));
}

// ------------------------------- conversions -------------------------------
__global__ void clear_flags()
{
    int i = blockIdx.x * blockDim.x + threadIdx.x;
    if (i < 2 * Bb * CHUNKS2) ((int*)g_fl)[i] = 0;
}

__global__ void conv_x_kern(const float* __restrict__ src) {
    int i = blockIdx.x * blockDim.x + threadIdx.x;   // over Mtot*Kd/4
    float4 v = ((const float4*)src)[i];
    __half hx = __float2half(v.x), hy = __float2half(v.y);
    __half hz = __float2half(v.z), hw = __float2half(v.w);
    __half lx = __float2half(v.x - __half2float(hx));
    __half ly = __float2half(v.y - __half2float(hy));
    __half lz = __float2half(v.z - __half2float(hz));
    __half lw = __float2half(v.w - __half2float(hw));
    __half2 p0; p0.x = hx; p0.y = hy;
    __half2 p1; p1.x = hz; p1.y = hw;
    __half2 q0; q0.x = lx; q0.y = ly;
    __half2 q1; q1.x = lz; q1.y = lw;
    ((__half2*)g_xh)[2*i  ] = p0;
    ((__half2*)g_xh)[2*i+1] = p1;
    ((__half2*)g_xl)[2*i  ] = q0;
    ((__half2*)g_xl)[2*i+1] = q1;
}

__global__ void conv_w_all(const float* __restrict__ w0, const float* __restrict__ w1,
                           const float* __restrict__ w2, const float* __restrict__ w3) {
    const float* srcs[4] = {w0, w1, w2, w3};
    const int wsel = blockIdx.y;
    int i = blockIdx.x * blockDim.x + threadIdx.x;   // over Kd*Hn/4
    float4 v = ((const float4*)srcs[wsel])[i];
    __half2 p0; p0.x = __float2half(v.x); p0.y = __float2half(v.y);
    __half2 p1; p1.x = __float2half(v.z); p1.y = __float2half(v.w);
    ((__half2*)g_w[wsel])[2*i  ] = p0;
    ((__half2*)g_w[wsel])[2*i+1] = p1;
}

// --------------------------- mma.sync dual GEMM -----------------------------
// CTA tile 128M x 64N; Z and H accumulators; fp16 2-term split (A hi/lo, W hi).
// 3-stage cp.async, single __syncthreads per chunk, 2 CTAs/SM.
// smem per stage: AH 0 (10240B), AL 10240, WZ 20480 (5120B), WH 25600.
// Row stride 40 fp16 (80B) — ldmatrix conflict-free.
#define KC 32
#define STAGES 3
#define STAGE_BYTES 30720
#define SMEM_BYTES (STAGES*STAGE_BYTES)
#define NCHUNK (Kd/KC)   // 16

__device__ __forceinline__ void load_stage(uint32_t sb,
    const __half* Ah, const __half* Al,
    const __half* Wz, const __half* Wh,
    int rowBase, int colBase, int kOff, int tid)
{
#pragma unroll
    for (int i = 0; i < 4; i++) {
        int idx  = tid + i * 256;        // 0..1023
        int tile = idx >> 9;             // 0=hi, 1=lo
        int r    = (idx >> 2) & 127;
        int seg  = idx & 3;
        const __half* src = (tile ? Al : Ah)
            + (size_t)(rowBase + r) * Kd + kOff + seg * 8;
        uint32_t dst = sb + tile * 10240 + r * 80 + seg * 16;
        cpa16(dst, src);
    }
#pragma unroll
    for (int i = 0; i < 2; i++) {
        int idx  = tid + i * 256;        // 0..511
        int tile = idx >> 8;             // 0=Wz, 1=Wh
        int r    = (idx >> 2) & 63;
        int seg  = idx & 3;
        const __half* src = (tile ? Wh : Wz)
            + (size_t)(colBase + r) * Kd + kOff + seg * 8;
        uint32_t dst = sb + 20480 + tile * 5120 + r * 80 + seg * 16;
        cpa16(dst, src);
    }
}

__global__ __launch_bounds__(256, 2)
void gemm_mma(int layer, const float* __restrict__ bz, const float* __restrict__ bh)
{
    extern __shared__ __align__(16) char sm[];
    const uint32_t sb = s2u(sm);

    const int tid  = threadIdx.x;
    const int lane = tid & 31;
    const int wid  = tid >> 5;
    const int gq   = lane >> 2;
    const int tq   = lane & 3;
    const int wm   = wid & 3;        // warp M block (32 rows)
    const int wn   = wid >> 2;       // warp N block (32 cols)

    const int rowBase = blockIdx.y * 128;
    const int colBase = blockIdx.x * 64;

    const __half* Wz = g_w[2 * layer + 0];
    const __half* Wh = g_w[2 * layer + 1];

    const uint32_t aLane = (uint32_t)((32 * wm + (lane & 15)) * 80 + ((lane >> 4) << 4));
    const uint32_t bLane = (uint32_t)(((32 * wn) + ((lane >> 4) << 3) + (lane & 7)) * 80
                                      + (((lane >> 3) & 1) << 4));

    float accZ[2][4][4];
    float accH[2][4][4];
#pragma unroll
    for (int mb = 0; mb < 2; mb++)
#pragma unroll
        for (int nb = 0; nb < 4; nb++)
#pragma unroll
            for (int r = 0; r < 4; r++) { accZ[mb][nb][r] = 0.f; accH[mb][nb][r] = 0.f; }

    // prologue: chunks 0,1 into stages 0,1
#pragma unroll
    for (int s = 0; s < 2; s++) {
        load_stage(sb + s * STAGE_BYTES, g_xh, g_xl, Wz, Wh, rowBase, colBase, s * KC, tid);
        asm volatile("cp.async.commit_group;" ::: "memory");
    }

    for (int c = 0; c < NCHUNK; c++) {
        if (c < NCHUNK - 1) asm volatile("cp.async.wait_group 1;" ::: "memory");
        else                asm volatile("cp.async.wait_group 0;" ::: "memory");
        __syncthreads();

        // issue next load before compute (buffer held chunk c-1, already consumed)
        if (c + 2 < NCHUNK) {
            load_stage(sb + ((c + 2) % STAGES) * STAGE_BYTES, g_xh, g_xl, Wz, Wh,
                       rowBase, colBase, (c + 2) * KC, tid);
            asm volatile("cp.async.commit_group;" ::: "memory");
        }

        const uint32_t stg = sb + (c % STAGES) * STAGE_BYTES;
        const uint32_t aH  = stg +     0 + aLane;
        const uint32_t aL  = stg + 10240 + aLane;
        const uint32_t bZ  = stg + 20480 + bLane;
        const uint32_t bH  = stg + 25600 + bLane;

#pragma unroll
        for (int ks = 0; ks < 2; ks++) {
            const uint32_t kb = (uint32_t)(ks * 32);   // 16 fp16 = 32 bytes
            uint32_t Afh[2][4], Afl[2][4];
#pragma unroll
            for (int mb = 0; mb < 2; mb++) {
                ldsm4(Afh[mb], aH + mb * (16 * 80) + kb);
                ldsm4(Afl[mb], aL + mb * (16 * 80) + kb);
            }
#pragma unroll
            for (int p = 0; p < 2; p++) {
                const uint32_t po = (uint32_t)(p * (16 * 80)) + kb;
                uint32_t zz[4], hh[4];
                ldsm4(zz, bZ + po);
                ldsm4(hh, bH + po);
#pragma unroll
                for (int q = 0; q < 2; q++) {
                    const int nb = 2 * p + q;
#pragma unroll
                    for (int mb = 0; mb < 2; mb++) {
                        mma_f16(accZ[mb][nb], Afh[mb], zz[2*q], zz[2*q+1]);
                        mma_f16(accZ[mb][nb], Afl[mb], zz[2*q], zz[2*q+1]);
                        mma_f16(accH[mb][nb], Afh[mb], hh[2*q], hh[2*q+1]);
                        mma_f16(accH[mb][nb], Afl[mb], hh[2*q], hh[2*q+1]);
                    }
                }
            }
        }
    }

    // ---------------------- fused activation epilogue ----------------------
#pragma unroll
    for (int mb = 0; mb < 2; mb++) {
        const int r0 = rowBase + 32 * wm + 16 * mb + gq;
#pragma unroll
        for (int nb = 0; nb < 4; nb++) {
            const int col = colBase + 32 * wn + 8 * nb + 2 * tq;
            const float bz0 = bz[col], bz1 = bz[col + 1];
            const float bh0 = bh[col], bh1 = bh[col + 1];
#pragma unroll
            for (int half = 0; half < 2; half++) {
                const int r = r0 + 8 * half;
                const float kv0 = accZ[mb][nb][2 * half]     + bz0;
                const float kv1 = accZ[mb][nb][2 * half + 1] + bz1;
                const float pv0 = accH[mb][nb][2 * half]     + bh0;
                const float pv1 = accH[mb][nb][2 * half + 1] + bh1;
                const float a0 = 1.0f / (1.0f + __expf(kv0));
                const float a1 = 1.0f / (1.0f + __expf(kv1));
                const float z0 = 1.0f / (1.0f + __expf(-kv0));
                const float z1 = 1.0f / (1.0f + __expf(-kv1));
                const float t0 = (pv0 >= 0.f) ? (pv0 + 0.5f)
                                              : (1.0f / (1.0f + __expf(-pv0)));
                const float t1 = (pv1 >= 0.f) ? (pv1 + 0.5f)
                                              : (1.0f / (1.0f + __expf(-pv1)));
                float4 v; v.x = a0; v.y = z0 * t0; v.z = a1; v.w = z1 * t1;
                *(float4*)&g_ab[(size_t)r * Hn + col] = v;
            }
        }
    }
}

// ------------------ single-pass scan with decoupled lookback ----------------
__global__ __launch_bounds__(512)
void scan_fused(int layer, float* __restrict__ out, float* __restrict__ finalDst)
{
    const int h = threadIdx.x;
    const int c = blockIdx.x;
    const int b = blockIdx.y;
    const size_t base = ((size_t)b * Ss + (size_t)c * TLEN2) * Hn + h;

    float2 v[TLEN2];
#pragma unroll
    for (int t = 0; t < TLEN2; t++)
        v[t] = __ldcg(&g_ab[base + (size_t)t * Hn]);

    float A = 1.f, Bv = 0.f;
#pragma unroll
    for (int t = 0; t < TLEN2; t++) {
        Bv = fmaf(v[t].x, Bv, v[t].y);
        A *= v[t].x;
    }

    const int cidx = b * CHUNKS2 + c;
    __shared__ int s_st;
    float hstart;

    if (c == 0) {
        hstart = 0.5f;
        float2 pub; pub.x = 0.f; pub.y = fmaf(A, hstart, Bv);
        __stcg(&g_inc[layer][(size_t)cidx * Hn + h], pub);
        __threadfence();
        __syncthreads();
        if (h == 0) atomicExch(&g_fl[layer][cidx], 2);
    } else {
        float2 pub; pub.x = A; pub.y = Bv;
        __stcg(&g_loc[layer][(size_t)cidx * Hn + h], pub);
        __threadfence();
        __syncthreads();
        if (h == 0) atomicExch(&g_fl[layer][cidx], 1);

        float alpha = 1.f, beta = 0.f;
        int p = c - 1;
        for (;;) {
            const int pidx = b * CHUNKS2 + p;
            if (h == 0) {
                int f;
                do { f = atomicAdd(&g_fl[layer][pidx], 0); } while (f == 0);
                s_st = f;
            }
            __syncthreads();
            const int stf = s_st;
            __syncthreads();
            if (stf == 2) {
                float2 pv = __ldcg(&g_inc[layer][(size_t)pidx * Hn + h]);
                hstart = fmaf(alpha, pv.y, beta);
                break;
            } else {
                float2 pv = __ldcg(&g_loc[layer][(size_t)pidx * Hn + h]);
                beta  = fmaf(alpha, pv.y, beta);
                alpha *= pv.x;
                p--;
            }
        }

        float2 pub2; pub2.x = 0.f; pub2.y = fmaf(A, hstart, Bv);
        __stcg(&g_inc[layer][(size_t)cidx * Hn + h], pub2);
        __threadfence();
        __syncthreads();
        if (h == 0) atomicExch(&g_fl[layer][cidx], 2);
    }

    float hv = hstart;
    if (layer == 0) {
#pragma unroll
        for (int t = 0; t < TLEN2; t++) {
            hv = fmaf(v[t].x, hv, v[t].y);
            size_t o = base + (size_t)t * Hn;
            __half hi = __float2half(hv);
            g_xh[o] = hi;
            g_xl[o] = __float2half(hv - __half2float(hi));
        }
    } else {
#pragma unroll
        for (int t = 0; t < TLEN2; t++) {
            hv = fmaf(v[t].x, hv, v[t].y);
            out[base + (size_t)t * Hn] = hv;
        }
    }
    if (c == CHUNKS2 - 1)
        finalDst[b * Hn + h] = hv;
}

// --------------------------------- launch ----------------------------------
extern "C" void kernel_launch(void* const* d_in, const int* in_sizes, int n_in,
                              void* d_out, int out_size)
{
    const float* x   = (const float*)d_in[0];
    const float* wz0 = (const float*)d_in[1];
    const float* bz0 = (const float*)d_in[2];
    const float* wh0 = (const float*)d_in[3];
    const float* bh0 = (const float*)d_in[4];
    const float* wz1 = (const float*)d_in[5];
    const float* bz1 = (const float*)d_in[6];
    const float* wh1 = (const float*)d_in[7];
    const float* bh1 = (const float*)d_in[8];

    float* out    = (float*)d_out;
    float* finals = out + (size_t)Mtot * Hn;

    static int smem_set = 0;
    if (!smem_set) {
        cudaFuncSetAttribute(gemm_mma, cudaFuncAttributeMaxDynamicSharedMemorySize,
                             SMEM_BYTES);
        smem_set = 1;
    }

    clear_flags<<<(2 * Bb * CHUNKS2 + 255) / 256, 256>>>();
    conv_x_kern<<<(Mtot * Kd / 4) / 256, 256>>>(x);
    conv_w_all<<<dim3((Kd * Hn / 4) / 256, 4), 256>>>(wz0, wh0, wz1, wh1);

    dim3 gg(Hn / 64, Mtot / 128);    // (8, 256)
    dim3 sg(CHUNKS2, Bb);            // (256, 8)

    gemm_mma<<<gg, 256, SMEM_BYTES>>>(0, bz0, bh0);
    scan_fused<<<sg, Hn>>>(0, nullptr, finals);

    gemm_mma<<<gg, 256, SMEM_BYTES>>>(1, bz1, bh1);
    scan_fused<<<sg, Hn>>>(1, out, finals + Bb * Hn);
}

// round 7
// speedup vs baseline: 2.6672x; 1.1350x over previous
#include <cuda_runtime.h>
#include <cuda_fp16.h>
#include <math.h>
#include <stdint.h>

#define Bb 8
#define Ss 4096
#define Hn 512
#define Kd 512
#define Mtot (Bb*Ss)          // 32768

#define CHUNKS2 256
#define TLEN2 (Ss/CHUNKS2)    // 16

// ------------------------- scratch (device globals) -------------------------
__device__ __align__(256) __half  g_xh[(size_t)Mtot*Kd];
__device__ __align__(256) __half  g_xl[(size_t)Mtot*Kd];
__device__ __align__(256) float2  g_ab[(size_t)Mtot*Hn];
__device__ __align__(256) float2  g_loc[2][Bb*CHUNKS2*Hn];
__device__ __align__(256) float2  g_inc[2][Bb*CHUNKS2*Hn];
__device__ __align__(256) int     g_fl [2][Bb*CHUNKS2];
// 0: wz0, 1: wh0, 2: wz1, 3: wh1 (fp16)
__device__ __align__(256) __half  g_w[4][(size_t)Kd*Hn];

// ------------------------------ helpers ------------------------------------
__device__ __forceinline__ uint32_t s2u(const void* p) {
    uint32_t a;
    asm("{ .reg .u64 t; cvta.to.shared.u64 t, %1; cvt.u32.u64 %0, t; }"
        : "=r"(a) : "l"(p));
    return a;
}

__device__ __forceinline__ void cpa16(uint32_t dst, const void* src) {
    asm volatile("cp.async.cg.shared.global [%0], [%1], 16;" :: "r"(dst), "l"(src));
}

__device__ __forceinline__ void mma_f16(float* d, const uint32_t* a,
                                        uint32_t b0, uint32_t b1) {
    asm volatile(
        "mma.sync.aligned.m16n8k16.row.col.f32.f16.f16.f32 "
        "{%0,%1,%2,%3}, {%4,%5,%6,%7}, {%8,%9}, {%0,%1,%2,%3};"
        : "+f"(d[0]), "+f"(d[1]), "+f"(d[2]), "+f"(d[3])
        : "r"(a[0]), "r"(a[1]), "r"(a[2]), "r"(a[3]), "r"(b0), "r"(b1));
}

__device__ __forceinline__ void ldsm4(uint32_t* r, uint32_t addr) {
    asm volatile("ldmatrix.sync.aligned.m8n8.x4.shared.b16 {%0,%1,%2,%3}, [%4];"
        : "=r"(r[0]), "=r"(r[1]), "=r"(r[2]), "=r"(r[3]) : "r"(addr));
}

// ------------------------------- conversions -------------------------------
__global__ void clear_flags()
{
    int i = blockIdx.x * blockDim.x + threadIdx.x;
    if (i < 2 * Bb * CHUNKS2) ((int*)g_fl)[i] = 0;
}

__global__ void conv_x_kern(const float* __restrict__ src) {
    int i = blockIdx.x * blockDim.x + threadIdx.x;   // over Mtot*Kd/4
    float4 v = ((const float4*)src)[i];
    __half hx = __float2half(v.x), hy = __float2half(v.y);
    __half hz = __float2half(v.z), hw = __float2half(v.w);
    __half lx = __float2half(v.x - __half2float(hx));
    __half ly = __float2half(v.y - __half2float(hy));
    __half lz = __float2half(v.z - __half2float(hz));
    __half lw = __float2half(v.w - __half2float(hw));
    __half2 p0; p0.x = hx; p0.y = hy;
    __half2 p1; p1.x = hz; p1.y = hw;
    __half2 q0; q0.x = lx; q0.y = ly;
    __half2 q1; q1.x = lz; q1.y = lw;
    ((__half2*)g_xh)[2*i  ] = p0;
    ((__half2*)g_xh)[2*i+1] = p1;
    ((__half2*)g_xl)[2*i  ] = q0;
    ((__half2*)g_xl)[2*i+1] = q1;
}

__global__ void conv_w_all(const float* __restrict__ w0, const float* __restrict__ w1,
                           const float* __restrict__ w2, const float* __restrict__ w3) {
    const float* srcs[4] = {w0, w1, w2, w3};
    const int wsel = blockIdx.y;
    int i = blockIdx.x * blockDim.x + threadIdx.x;   // over Kd*Hn/4
    float4 v = ((const float4*)srcs[wsel])[i];
    __half2 p0; p0.x = __float2half(v.x); p0.y = __float2half(v.y);
    __half2 p1; p1.x = __float2half(v.z); p1.y = __float2half(v.w);
    ((__half2*)g_w[wsel])[2*i  ] = p0;
    ((__half2*)g_w[wsel])[2*i+1] = p1;
}

// --------------------------- mma.sync dual GEMM -----------------------------
#define KC 32
#define STAGES 3
#define STAGE_BYTES 30720
#define SMEM_BYTES (STAGES*STAGE_BYTES)
#define NCHUNK (Kd/KC)   // 16

__device__ __forceinline__ void load_stage(uint32_t sb,
    const __half* Ah, const __half* Al,
    const __half* Wz, const __half* Wh,
    int rowBase, int colBase, int kOff, int tid)
{
#pragma unroll
    for (int i = 0; i < 4; i++) {
        int idx  = tid + i * 256;        // 0..1023
        int tile = idx >> 9;             // 0=hi, 1=lo
        int r    = (idx >> 2) & 127;
        int seg  = idx & 3;
        const __half* src = (tile ? Al : Ah)
            + (size_t)(rowBase + r) * Kd + kOff + seg * 8;
        uint32_t dst = sb + tile * 10240 + r * 80 + seg * 16;
        cpa16(dst, src);
    }
#pragma unroll
    for (int i = 0; i < 2; i++) {
        int idx  = tid + i * 256;        // 0..511
        int tile = idx >> 8;             // 0=Wz, 1=Wh
        int r    = (idx >> 2) & 63;
        int seg  = idx & 3;
        const __half* src = (tile ? Wh : Wz)
            + (size_t)(colBase + r) * Kd + kOff + seg * 8;
        uint32_t dst = sb + 20480 + tile * 5120 + r * 80 + seg * 16;
        cpa16(dst, src);
    }
}

__global__ __launch_bounds__(256, 2)
void gemm_mma(int layer, const float* __restrict__ bz, const float* __restrict__ bh)
{
    extern __shared__ __align__(16) char sm[];
    const uint32_t sb = s2u(sm);

    const int tid  = threadIdx.x;
    const int lane = tid & 31;
    const int wid  = tid >> 5;
    const int gq   = lane >> 2;
    const int tq   = lane & 3;
    const int wm   = wid & 3;
    const int wn   = wid >> 2;

    const int rowBase = blockIdx.y * 128;
    const int colBase = blockIdx.x * 64;

    const __half* Wz = g_w[2 * layer + 0];
    const __half* Wh = g_w[2 * layer + 1];

    const uint32_t aLane = (uint32_t)((32 * wm + (lane & 15)) * 80 + ((lane >> 4) << 4));
    const uint32_t bLane = (uint32_t)(((32 * wn) + ((lane >> 4) << 3) + (lane & 7)) * 80
                                      + (((lane >> 3) & 1) << 4));

    float accZ[2][4][4];
    float accH[2][4][4];
#pragma unroll
    for (int mb = 0; mb < 2; mb++)
#pragma unroll
        for (int nb = 0; nb < 4; nb++)
#pragma unroll
            for (int r = 0; r < 4; r++) { accZ[mb][nb][r] = 0.f; accH[mb][nb][r] = 0.f; }

#pragma unroll
    for (int s = 0; s < 2; s++) {
        load_stage(sb + s * STAGE_BYTES, g_xh, g_xl, Wz, Wh, rowBase, colBase, s * KC, tid);
        asm volatile("cp.async.commit_group;" ::: "memory");
    }

    for (int c = 0; c < NCHUNK; c++) {
        if (c < NCHUNK - 1) asm volatile("cp.async.wait_group 1;" ::: "memory");
        else                asm volatile("cp.async.wait_group 0;" ::: "memory");
        __syncthreads();

        if (c + 2 < NCHUNK) {
            load_stage(sb + ((c + 2) % STAGES) * STAGE_BYTES, g_xh, g_xl, Wz, Wh,
                       rowBase, colBase, (c + 2) * KC, tid);
            asm volatile("cp.async.commit_group;" ::: "memory");
        }

        const uint32_t stg = sb + (c % STAGES) * STAGE_BYTES;
        const uint32_t aH  = stg +     0 + aLane;
        const uint32_t aL  = stg + 10240 + aLane;
        const uint32_t bZ  = stg + 20480 + bLane;
        const uint32_t bH  = stg + 25600 + bLane;

#pragma unroll
        for (int ks = 0; ks < 2; ks++) {
            const uint32_t kb = (uint32_t)(ks * 32);
            uint32_t Afh[2][4], Afl[2][4], zz[2][4], hh[2][4];
            // all fragment loads first
#pragma unroll
            for (int mb = 0; mb < 2; mb++) {
                ldsm4(Afh[mb], aH + mb * (16 * 80) + kb);
                ldsm4(Afl[mb], aL + mb * (16 * 80) + kb);
            }
#pragma unroll
            for (int p = 0; p < 2; p++) {
                ldsm4(zz[p], bZ + p * (16 * 80) + kb);
                ldsm4(hh[p], bH + p * (16 * 80) + kb);
            }
            // hi term: 16 MMAs, all-independent accumulators
#pragma unroll
            for (int p = 0; p < 2; p++)
#pragma unroll
                for (int q = 0; q < 2; q++)
#pragma unroll
                    for (int mb = 0; mb < 2; mb++) {
                        const int nb = 2 * p + q;
                        mma_f16(accZ[mb][nb], Afh[mb], zz[p][2*q], zz[p][2*q+1]);
                        mma_f16(accH[mb][nb], Afh[mb], hh[p][2*q], hh[p][2*q+1]);
                    }
            // lo term
#pragma unroll
            for (int p = 0; p < 2; p++)
#pragma unroll
                for (int q = 0; q < 2; q++)
#pragma unroll
                    for (int mb = 0; mb < 2; mb++) {
                        const int nb = 2 * p + q;
                        mma_f16(accZ[mb][nb], Afl[mb], zz[p][2*q], zz[p][2*q+1]);
                        mma_f16(accH[mb][nb], Afl[mb], hh[p][2*q], hh[p][2*q+1]);
                    }
        }
    }

    // ---------------------- fused activation epilogue ----------------------
#pragma unroll
    for (int mb = 0; mb < 2; mb++) {
        const int r0 = rowBase + 32 * wm + 16 * mb + gq;
#pragma unroll
        for (int nb = 0; nb < 4; nb++) {
            const int col = colBase + 32 * wn + 8 * nb + 2 * tq;
            const float bz0 = bz[col], bz1 = bz[col + 1];
            const float bh0 = bh[col], bh1 = bh[col + 1];
#pragma unroll
            for (int half = 0; half < 2; half++) {
                const int r = r0 + 8 * half;
                const float kv0 = accZ[mb][nb][2 * half]     + bz0;
                const float kv1 = accZ[mb][nb][2 * half + 1] + bz1;
                const float pv0 = accH[mb][nb][2 * half]     + bh0;
                const float pv1 = accH[mb][nb][2 * half + 1] + bh1;
                const float a0 = 1.0f / (1.0f + __expf(kv0));
                const float a1 = 1.0f / (1.0f + __expf(kv1));
                const float z0 = 1.0f / (1.0f + __expf(-kv0));
                const float z1 = 1.0f / (1.0f + __expf(-kv1));
                const float t0 = (pv0 >= 0.f) ? (pv0 + 0.5f)
                                              : (1.0f / (1.0f + __expf(-pv0)));
                const float t1 = (pv1 >= 0.f) ? (pv1 + 0.5f)
                                              : (1.0f / (1.0f + __expf(-pv1)));
                float4 v; v.x = a0; v.y = z0 * t0; v.z = a1; v.w = z1 * t1;
                *(float4*)&g_ab[(size_t)r * Hn + col] = v;
            }
        }
    }
}

// --------- single-pass scan, warp-parallel decoupled lookback ---------------
__global__ __launch_bounds__(512)
void scan_fused(int layer, float* __restrict__ out, float* __restrict__ finalDst)
{
    const int h = threadIdx.x;
    const int c = blockIdx.x;
    const int b = blockIdx.y;
    const int lane = h & 31;
    const size_t base = ((size_t)b * Ss + (size_t)c * TLEN2) * Hn + h;

    float2 v[TLEN2];
#pragma unroll
    for (int t = 0; t < TLEN2; t++)
        v[t] = __ldcs(&g_ab[base + (size_t)t * Hn]);

    float A = 1.f, Bv = 0.f;
#pragma unroll
    for (int t = 0; t < TLEN2; t++) {
        Bv = fmaf(v[t].x, Bv, v[t].y);
        A *= v[t].x;
    }

    const int cidx = b * CHUNKS2 + c;
    __shared__ int s_n, s_f2;
    float hstart;

    if (c == 0) {
        hstart = 0.5f;
        float2 pub; pub.x = 0.f; pub.y = fmaf(A, hstart, Bv);
        __stcg(&g_inc[layer][(size_t)cidx * Hn + h], pub);
        __threadfence();
        __syncthreads();
        if (h == 0) atomicExch(&g_fl[layer][cidx], 2);
    } else {
        float2 pub; pub.x = A; pub.y = Bv;
        __stcg(&g_loc[layer][(size_t)cidx * Hn + h], pub);
        __threadfence();
        __syncthreads();
        if (h == 0) atomicExch(&g_fl[layer][cidx], 1);

        // warp-parallel lookback: window of up to 32 predecessors per round
        float alpha = 1.f, beta = 0.f;
        int p = c - 1;
        for (;;) {
            if (h < 32) {
                int rel = p - lane;
                int f = 0;
                if (rel >= 0) f = atomicAdd(&g_fl[layer][b * CHUNKS2 + rel], 0);
                unsigned m0 = __ballot_sync(0xffffffffu, f == 0);
                unsigned m2 = __ballot_sync(0xffffffffu, f == 2);
                int n = m0 ? (__ffs(m0) - 1) : 32;
                unsigned lim = (n >= 32) ? 0xffffffffu : ((1u << n) - 1u);
                unsigned m2v = m2 & lim;
                int f2 = m2v ? (__ffs(m2v) - 1) : -1;
                if (lane == 0) { s_n = n; s_f2 = f2; }
            }
            __syncthreads();
            const int n = s_n, f2 = s_f2;
            __syncthreads();

            if (f2 >= 0) {
                for (int l = 0; l < f2; l++) {
                    float2 pv = __ldcg(&g_loc[layer][(size_t)(b * CHUNKS2 + p - l) * Hn + h]);
                    beta  = fmaf(alpha, pv.y, beta);
                    alpha *= pv.x;
                }
                float2 iv = __ldcg(&g_inc[layer][(size_t)(b * CHUNKS2 + p - f2) * Hn + h]);
                hstart = fmaf(alpha, iv.y, beta);
                break;
            }
            for (int l = 0; l < n; l++) {
                float2 pv = __ldcg(&g_loc[layer][(size_t)(b * CHUNKS2 + p - l) * Hn + h]);
                beta  = fmaf(alpha, pv.y, beta);
                alpha *= pv.x;
            }
            p -= n;
        }

        float2 pub2; pub2.x = 0.f; pub2.y = fmaf(A, hstart, Bv);
        __stcg(&g_inc[layer][(size_t)cidx * Hn + h], pub2);
        __threadfence();
        __syncthreads();
        if (h == 0) atomicExch(&g_fl[layer][cidx], 2);
    }

    float hv = hstart;
    if (layer == 0) {
#pragma unroll
        for (int t = 0; t < TLEN2; t++) {
            hv = fmaf(v[t].x, hv, v[t].y);
            size_t o = base + (size_t)t * Hn;
            __half hi = __float2half(hv);
            g_xh[o] = hi;
            g_xl[o] = __float2half(hv - __half2float(hi));
        }
    } else {
#pragma unroll
        for (int t = 0; t < TLEN2; t++) {
            hv = fmaf(v[t].x, hv, v[t].y);
            __stcs(&out[base + (size_t)t * Hn], hv);
        }
    }
    if (c == CHUNKS2 - 1)
        finalDst[b * Hn + h] = hv;
}

// --------------------------------- launch ----------------------------------
extern "C" void kernel_launch(void* const* d_in, const int* in_sizes, int n_in,
                              void* d_out, int out_size)
{
    const float* x   = (const float*)d_in[0];
    const float* wz0 = (const float*)d_in[1];
    const float* bz0 = (const float*)d_in[2];
    const float* wh0 = (const float*)d_in[3];
    const float* bh0 = (const float*)d_in[4];
    const float* wz1 = (const float*)d_in[5];
    const float* bz1 = (const float*)d_in[6];
    const float* wh1 = (const float*)d_in[7];
    const float* bh1 = (const float*)d_in[8];

    float* out    = (float*)d_out;
    float* finals = out + (size_t)Mtot * Hn;

    static int smem_set = 0;
    if (!smem_set) {
        cudaFuncSetAttribute(gemm_mma, cudaFuncAttributeMaxDynamicSharedMemorySize,
                             SMEM_BYTES);
        smem_set = 1;
    }

    clear_flags<<<(2 * Bb * CHUNKS2 + 255) / 256, 256>>>();
    conv_x_kern<<<(Mtot * Kd / 4) / 256, 256>>>(x);
    conv_w_all<<<dim3((Kd * Hn / 4) / 256, 4), 256>>>(wz0, wh0, wz1, wh1);

    dim3 gg(Hn / 64, Mtot / 128);    // (8, 256)
    dim3 sg(CHUNKS2, Bb);            // (256, 8)

    gemm_mma<<<gg, 256, SMEM_BYTES>>>(0, bz0, bh0);
    scan_fused<<<sg, Hn>>>(0, nullptr, finals);

    gemm_mma<<<gg, 256, SMEM_BYTES>>>(1, bz1, bh1);
    scan_fused<<<sg, Hn>>>(1, out, finals + Bb * Hn);
}

// round 8
// speedup vs baseline: 3.5621x; 1.3355x over previous
#include <cuda_runtime.h>
#include <cuda_fp16.h>
#include <math.h>
#include <stdint.h>

#define Bb 8
#define Ss 4096
#define Hn 512
#define Kd 512
#define Mtot (Bb*Ss)          // 32768

#define CHUNKS2 256
#define TLEN2 (Ss/CHUNKS2)    // 16

// ------------------------- scratch (device globals) -------------------------
__device__ __align__(256) __half  g_xh[(size_t)Mtot*Kd];
__device__ __align__(256) float2  g_ab[(size_t)Mtot*Hn];
__device__ __align__(256) float2  g_loc[2][Bb*CHUNKS2*Hn];
__device__ __align__(256) float2  g_inc[2][Bb*CHUNKS2*Hn];
__device__ __align__(256) int     g_fl [2][Bb*CHUNKS2];
// 0: wz0, 1: wh0, 2: wz1, 3: wh1 (fp16)
__device__ __align__(256) __half  g_w[4][(size_t)Kd*Hn];

// ------------------------------ helpers ------------------------------------
__device__ __forceinline__ uint32_t s2u(const void* p) {
    uint32_t a;
    asm("{ .reg .u64 t; cvta.to.shared.u64 t, %1; cvt.u32.u64 %0, t; }"
        : "=r"(a) : "l"(p));
    return a;
}

__device__ __forceinline__ void cpa16(uint32_t dst, const void* src) {
    asm volatile("cp.async.cg.shared.global [%0], [%1], 16;" :: "r"(dst), "l"(src));
}

__device__ __forceinline__ void mma_f16(float* d, const uint32_t* a,
                                        uint32_t b0, uint32_t b1) {
    asm volatile(
        "mma.sync.aligned.m16n8k16.row.col.f32.f16.f16.f32 "
        "{%0,%1,%2,%3}, {%4,%5,%6,%7}, {%8,%9}, {%0,%1,%2,%3};"
        : "+f"(d[0]), "+f"(d[1]), "+f"(d[2]), "+f"(d[3])
        : "r"(a[0]), "r"(a[1]), "r"(a[2]), "r"(a[3]), "r"(b0), "r"(b1));
}

__device__ __forceinline__ void ldsm4(uint32_t* r, uint32_t addr) {
    asm volatile("ldmatrix.sync.aligned.m8n8.x4.shared.b16 {%0,%1,%2,%3}, [%4];"
        : "=r"(r[0]), "=r"(r[1]), "=r"(r[2]), "=r"(r[3]) : "r"(addr));
}

// ------------------------------- conversions -------------------------------
__global__ void clear_flags()
{
    int i = blockIdx.x * blockDim.x + threadIdx.x;
    if (i < 2 * Bb * CHUNKS2) ((int*)g_fl)[i] = 0;
}

__global__ void conv_x_kern(const float* __restrict__ src) {
    int i = blockIdx.x * blockDim.x + threadIdx.x;   // over Mtot*Kd/4
    float4 v = ((const float4*)src)[i];
    __half2 p0 = __floats2half2_rn(v.x, v.y);
    __half2 p1 = __floats2half2_rn(v.z, v.w);
    ((__half2*)g_xh)[2*i  ] = p0;
    ((__half2*)g_xh)[2*i+1] = p1;
}

__global__ void conv_w_all(const float* __restrict__ w0, const float* __restrict__ w1,
                           const float* __restrict__ w2, const float* __restrict__ w3) {
    const float* srcs[4] = {w0, w1, w2, w3};
    const int wsel = blockIdx.y;
    int i = blockIdx.x * blockDim.x + threadIdx.x;   // over Kd*Hn/4
    float4 v = ((const float4*)srcs[wsel])[i];
    __half2 p0 = __floats2half2_rn(v.x, v.y);
    __half2 p1 = __floats2half2_rn(v.z, v.w);
    ((__half2*)g_w[wsel])[2*i  ] = p0;
    ((__half2*)g_w[wsel])[2*i+1] = p1;
}

// --------------------------- mma.sync dual GEMM -----------------------------
// CTA tile 128M x 64N; Z and H accumulators; plain fp16 operands.
// 4-stage cp.async pipeline, 2 CTAs/SM.
// smem per stage: A 0 (10240B), WZ 10240 (5120B), WH 15360 (5120B).
// Row stride 40 fp16 (80B) — ldmatrix conflict-free.
#define KC 32
#define STAGES 4
#define STAGE_BYTES 20480
#define SMEM_BYTES (STAGES*STAGE_BYTES)
#define NCHUNK (Kd/KC)   // 16

__device__ __forceinline__ void load_stage(uint32_t sb,
    const __half* Ax, const __half* Wz, const __half* Wh,
    int rowBase, int colBase, int kOff, int tid)
{
#pragma unroll
    for (int i = 0; i < 2; i++) {
        int idx = tid + i * 256;         // 0..511
        int r   = idx >> 2;              // 0..127
        int seg = idx & 3;
        const __half* src = Ax + (size_t)(rowBase + r) * Kd + kOff + seg * 8;
        cpa16(sb + r * 80 + seg * 16, src);
    }
#pragma unroll
    for (int i = 0; i < 2; i++) {
        int idx  = tid + i * 256;        // 0..511
        int tile = idx >> 8;             // 0=Wz, 1=Wh
        int r    = (idx >> 2) & 63;
        int seg  = idx & 3;
        const __half* src = (tile ? Wh : Wz)
            + (size_t)(colBase + r) * Kd + kOff + seg * 8;
        cpa16(sb + 10240 + tile * 5120 + r * 80 + seg * 16, src);
    }
}

__global__ __launch_bounds__(256, 2)
void gemm_mma(int layer, const float* __restrict__ bz, const float* __restrict__ bh)
{
    extern __shared__ __align__(16) char sm[];
    const uint32_t sb = s2u(sm);

    const int tid  = threadIdx.x;
    const int lane = tid & 31;
    const int wid  = tid >> 5;
    const int gq   = lane >> 2;
    const int tq   = lane & 3;
    const int wm   = wid & 3;
    const int wn   = wid >> 2;

    const int rowBase = blockIdx.y * 128;
    const int colBase = blockIdx.x * 64;

    const __half* Wz = g_w[2 * layer + 0];
    const __half* Wh = g_w[2 * layer + 1];

    const uint32_t aLane = (uint32_t)((32 * wm + (lane & 15)) * 80 + ((lane >> 4) << 4));
    const uint32_t bLane = (uint32_t)(((32 * wn) + ((lane >> 4) << 3) + (lane & 7)) * 80
                                      + (((lane >> 3) & 1) << 4));

    float accZ[2][4][4];
    float accH[2][4][4];
#pragma unroll
    for (int mb = 0; mb < 2; mb++)
#pragma unroll
        for (int nb = 0; nb < 4; nb++)
#pragma unroll
            for (int r = 0; r < 4; r++) { accZ[mb][nb][r] = 0.f; accH[mb][nb][r] = 0.f; }

    // prologue: chunks 0..2 into stages 0..2
#pragma unroll
    for (int s = 0; s < 3; s++) {
        load_stage(sb + s * STAGE_BYTES, g_xh, Wz, Wh, rowBase, colBase, s * KC, tid);
        asm volatile("cp.async.commit_group;" ::: "memory");
    }

    for (int c = 0; c < NCHUNK; c++) {
        if (c < NCHUNK - 2)      asm volatile("cp.async.wait_group 2;" ::: "memory");
        else if (c == NCHUNK - 2) asm volatile("cp.async.wait_group 1;" ::: "memory");
        else                      asm volatile("cp.async.wait_group 0;" ::: "memory");
        __syncthreads();

        if (c + 3 < NCHUNK) {
            load_stage(sb + ((c + 3) % STAGES) * STAGE_BYTES, g_xh, Wz, Wh,
                       rowBase, colBase, (c + 3) * KC, tid);
            asm volatile("cp.async.commit_group;" ::: "memory");
        }

        const uint32_t stg = sb + (c % STAGES) * STAGE_BYTES;
        const uint32_t aA  = stg +     0 + aLane;
        const uint32_t bZ  = stg + 10240 + bLane;
        const uint32_t bH  = stg + 15360 + bLane;

#pragma unroll
        for (int ks = 0; ks < 2; ks++) {
            const uint32_t kb = (uint32_t)(ks * 32);
            uint32_t Af[2][4], zz[2][4], hh[2][4];
#pragma unroll
            for (int mb = 0; mb < 2; mb++)
                ldsm4(Af[mb], aA + mb * (16 * 80) + kb);
#pragma unroll
            for (int p = 0; p < 2; p++) {
                ldsm4(zz[p], bZ + p * (16 * 80) + kb);
                ldsm4(hh[p], bH + p * (16 * 80) + kb);
            }
#pragma unroll
            for (int p = 0; p < 2; p++)
#pragma unroll
                for (int q = 0; q < 2; q++)
#pragma unroll
                    for (int mb = 0; mb < 2; mb++) {
                        const int nb = 2 * p + q;
                        mma_f16(accZ[mb][nb], Af[mb], zz[p][2*q], zz[p][2*q+1]);
                        mma_f16(accH[mb][nb], Af[mb], hh[p][2*q], hh[p][2*q+1]);
                    }
        }
    }

    // ---------------------- fused activation epilogue ----------------------
#pragma unroll
    for (int mb = 0; mb < 2; mb++) {
        const int r0 = rowBase + 32 * wm + 16 * mb + gq;
#pragma unroll
        for (int nb = 0; nb < 4; nb++) {
            const int col = colBase + 32 * wn + 8 * nb + 2 * tq;
            const float bz0 = bz[col], bz1 = bz[col + 1];
            const float bh0 = bh[col], bh1 = bh[col + 1];
#pragma unroll
            for (int half = 0; half < 2; half++) {
                const int r = r0 + 8 * half;
                const float kv0 = accZ[mb][nb][2 * half]     + bz0;
                const float kv1 = accZ[mb][nb][2 * half + 1] + bz1;
                const float pv0 = accH[mb][nb][2 * half]     + bh0;
                const float pv1 = accH[mb][nb][2 * half + 1] + bh1;
                const float a0 = 1.0f / (1.0f + __expf(kv0));
                const float a1 = 1.0f / (1.0f + __expf(kv1));
                const float z0 = 1.0f / (1.0f + __expf(-kv0));
                const float z1 = 1.0f / (1.0f + __expf(-kv1));
                const float t0 = (pv0 >= 0.f) ? (pv0 + 0.5f)
                                              : (1.0f / (1.0f + __expf(-pv0)));
                const float t1 = (pv1 >= 0.f) ? (pv1 + 0.5f)
                                              : (1.0f / (1.0f + __expf(-pv1)));
                float4 v; v.x = a0; v.y = z0 * t0; v.z = a1; v.w = z1 * t1;
                *(float4*)&g_ab[(size_t)r * Hn + col] = v;
            }
        }
    }
}

// --------- single-pass scan, warp-parallel decoupled lookback ---------------
__global__ __launch_bounds__(512)
void scan_fused(int layer, float* __restrict__ out, float* __restrict__ finalDst)
{
    const int h = threadIdx.x;
    const int c = blockIdx.x;
    const int b = blockIdx.y;
    const int lane = h & 31;
    const size_t base = ((size_t)b * Ss + (size_t)c * TLEN2) * Hn + h;

    float2 v[TLEN2];
#pragma unroll
    for (int t = 0; t < TLEN2; t++)
        v[t] = __ldcs(&g_ab[base + (size_t)t * Hn]);

    float A = 1.f, Bv = 0.f;
#pragma unroll
    for (int t = 0; t < TLEN2; t++) {
        Bv = fmaf(v[t].x, Bv, v[t].y);
        A *= v[t].x;
    }

    const int cidx = b * CHUNKS2 + c;
    __shared__ int s_n, s_f2;
    float hstart;

    if (c == 0) {
        hstart = 0.5f;
        float2 pub; pub.x = 0.f; pub.y = fmaf(A, hstart, Bv);
        __stcg(&g_inc[layer][(size_t)cidx * Hn + h], pub);
        __threadfence();
        __syncthreads();
        if (h == 0) atomicExch(&g_fl[layer][cidx], 2);
    } else {
        float2 pub; pub.x = A; pub.y = Bv;
        __stcg(&g_loc[layer][(size_t)cidx * Hn + h], pub);
        __threadfence();
        __syncthreads();
        if (h == 0) atomicExch(&g_fl[layer][cidx], 1);

        float alpha = 1.f, beta = 0.f;
        int p = c - 1;
        for (;;) {
            if (h < 32) {
                int rel = p - lane;
                int f = 0;
                if (rel >= 0) f = atomicAdd(&g_fl[layer][b * CHUNKS2 + rel], 0);
                unsigned m0 = __ballot_sync(0xffffffffu, f == 0);
                unsigned m2 = __ballot_sync(0xffffffffu, f == 2);
                int n = m0 ? (__ffs(m0) - 1) : 32;
                unsigned lim = (n >= 32) ? 0xffffffffu : ((1u << n) - 1u);
                unsigned m2v = m2 & lim;
                int f2 = m2v ? (__ffs(m2v) - 1) : -1;
                if (lane == 0) { s_n = n; s_f2 = f2; }
            }
            __syncthreads();
            const int n = s_n, f2 = s_f2;
            __syncthreads();

            if (f2 >= 0) {
                for (int l = 0; l < f2; l++) {
                    float2 pv = __ldcg(&g_loc[layer][(size_t)(b * CHUNKS2 + p - l) * Hn + h]);
                    beta  = fmaf(alpha, pv.y, beta);
                    alpha *= pv.x;
                }
                float2 iv = __ldcg(&g_inc[layer][(size_t)(b * CHUNKS2 + p - f2) * Hn + h]);
                hstart = fmaf(alpha, iv.y, beta);
                break;
            }
            for (int l = 0; l < n; l++) {
                float2 pv = __ldcg(&g_loc[layer][(size_t)(b * CHUNKS2 + p - l) * Hn + h]);
                beta  = fmaf(alpha, pv.y, beta);
                alpha *= pv.x;
            }
            p -= n;
        }

        float2 pub2; pub2.x = 0.f; pub2.y = fmaf(A, hstart, Bv);
        __stcg(&g_inc[layer][(size_t)cidx * Hn + h], pub2);
        __threadfence();
        __syncthreads();
        if (h == 0) atomicExch(&g_fl[layer][cidx], 2);
    }

    float hv = hstart;
    if (layer == 0) {
#pragma unroll
        for (int t = 0; t < TLEN2; t++) {
            hv = fmaf(v[t].x, hv, v[t].y);
            g_xh[base + (size_t)t * Hn] = __float2half(hv);
        }
    } else {
#pragma unroll
        for (int t = 0; t < TLEN2; t++) {
            hv = fmaf(v[t].x, hv, v[t].y);
            __stcs(&out[base + (size_t)t * Hn], hv);
        }
    }
    if (c == CHUNKS2 - 1)
        finalDst[b * Hn + h] = hv;
}

// --------------------------------- launch ----------------------------------
extern "C" void kernel_launch(void* const* d_in, const int* in_sizes, int n_in,
                              void* d_out, int out_size)
{
    const float* x   = (const float*)d_in[0];
    const float* wz0 = (const float*)d_in[1];
    const float* bz0 = (const float*)d_in[2];
    const float* wh0 = (const float*)d_in[3];
    const float* bh0 = (const float*)d_in[4];
    const float* wz1 = (const float*)d_in[5];
    const float* bz1 = (const float*)d_in[6];
    const float* wh1 = (const float*)d_in[7];
    const float* bh1 = (const float*)d_in[8];

    float* out    = (float*)d_out;
    float* finals = out + (size_t)Mtot * Hn;

    static int smem_set = 0;
    if (!smem_set) {
        cudaFuncSetAttribute(gemm_mma, cudaFuncAttributeMaxDynamicSharedMemorySize,
                             SMEM_BYTES);
        smem_set = 1;
    }

    clear_flags<<<(2 * Bb * CHUNKS2 + 255) / 256, 256>>>();
    conv_x_kern<<<(Mtot * Kd / 4) / 256, 256>>>(x);
    conv_w_all<<<dim3((Kd * Hn / 4) / 256, 4), 256>>>(wz0, wh0, wz1, wh1);

    dim3 gg(Hn / 64, Mtot / 128);    // (8, 256)
    dim3 sg(CHUNKS2, Bb);            // (256, 8)

    gemm_mma<<<gg, 256, SMEM_BYTES>>>(0, bz0, bh0);
    scan_fused<<<sg, Hn>>>(0, nullptr, finals);

    gemm_mma<<<gg, 256, SMEM_BYTES>>>(1, bz1, bh1);
    scan_fused<<<sg, Hn>>>(1, out, finals + Bb * Hn);
}